// round 15
// baseline (speedup 1.0000x reference)
#include <cuda_runtime.h>
#include <cuda_bf16.h>
#include <mma.h>
#include <cstdint>

using namespace nvcuda;
typedef __nv_bfloat16 bf16;

// Problem dims
constexpr int Bc  = 4;
constexpr int Lc  = 512;
constexpr int Dc  = 2048;
constexpr int Hc  = 16;
constexpr int Cc  = 128;
constexpr int KVc = 2048;
constexpr int Kc  = 1024;   // T*LA

// ---------------------------------------------------------------------------
// Scratch (device globals — allocation-free rule)
// ---------------------------------------------------------------------------
__device__ bf16  g_xk_hi[(size_t)Bc * Kc * KVc];
__device__ bf16  g_xk_lo[(size_t)Bc * Kc * KVc];
__device__ bf16  g_lat_hi[(size_t)Bc * Lc * Dc];
__device__ bf16  g_lat_lo[(size_t)Bc * Lc * Dc];
__device__ bf16  g_q_hi[(size_t)Bc * Lc * Dc];
__device__ bf16  g_q_lo[(size_t)Bc * Lc * Dc];
__device__ bf16  g_kv_hi[(size_t)Bc * Kc * 2 * Dc];
__device__ bf16  g_kv_lo[(size_t)Bc * Kc * 2 * Dc];
__device__ bf16  g_at_hi[(size_t)Bc * Lc * Dc];
__device__ bf16  g_at_lo[(size_t)Bc * Lc * Dc];
__device__ bf16  g_wq_hi[(size_t)Dc * Dc];
__device__ bf16  g_wq_lo[(size_t)Dc * Dc];
__device__ bf16  g_wkv_hi[(size_t)KVc * 2 * Dc];
__device__ bf16  g_wkv_lo[(size_t)KVc * 2 * Dc];
__device__ bf16  g_wo_hi[(size_t)Dc * Dc];
__device__ bf16  g_wo_lo[(size_t)Dc * Dc];

// ---------------------------------------------------------------------------
// Helpers
// ---------------------------------------------------------------------------
__device__ __forceinline__ void cp_async16(void* smem_dst, const void* gmem_src) {
    unsigned s = (unsigned)__cvta_generic_to_shared(smem_dst);
    asm volatile("cp.async.cg.shared.global [%0], [%1], 16;\n" :: "r"(s), "l"(gmem_src));
}
__device__ __forceinline__ void cp_commit() { asm volatile("cp.async.commit_group;\n"); }
__device__ __forceinline__ void cp_wait0()  { asm volatile("cp.async.wait_group 0;\n"); }
__device__ __forceinline__ void cp_wait1()  { asm volatile("cp.async.wait_group 1;\n"); }
__device__ __forceinline__ void cp_wait2()  { asm volatile("cp.async.wait_group 2;\n"); }

struct __align__(8) bf4 { bf16 v[4]; };
__device__ __forceinline__ void split_store4(bf16* hi, bf16* lo, size_t off, float4 f) {
    bf4 H, L;
    float ff[4] = { f.x, f.y, f.z, f.w };
    #pragma unroll
    for (int e = 0; e < 4; e++) {
        bf16 h = __float2bfloat16(ff[e]);
        H.v[e] = h;
        L.v[e] = __float2bfloat16(ff[e] - __bfloat162float(h));
    }
    *reinterpret_cast<bf4*>(hi + off) = H;
    *reinterpret_cast<bf4*>(lo + off) = L;
}

__device__ __forceinline__ float warp_sum(float v) {
    #pragma unroll
    for (int o = 16; o > 0; o >>= 1) v += __shfl_xor_sync(0xffffffffu, v, o);
    return v;
}
__device__ __forceinline__ float block_sum256(float v, float* red) {
    int lane = threadIdx.x & 31, w = threadIdx.x >> 5;
    v = warp_sum(v);
    if (lane == 0) red[w] = v;
    __syncthreads();
    if (w == 0) {
        float t = (lane < 8) ? red[lane] : 0.0f;
        t = warp_sum(t);
        if (lane == 0) red[32] = t;
    }
    __syncthreads();
    float r = red[32];
    __syncthreads();
    return r;
}

// ---------------------------------------------------------------------------
// fp32 -> bf16 hi/lo splitter (weights)
// ---------------------------------------------------------------------------
__global__ void split_kernel(const float* __restrict__ W,
                             bf16* __restrict__ hi, bf16* __restrict__ lo,
                             int total4) {
    int i = blockIdx.x * blockDim.x + threadIdx.x;
    const int stride = gridDim.x * blockDim.x;
    for (; i < total4; i += stride) {
        float4 v = reinterpret_cast<const float4*>(W)[i];
        split_store4(hi, lo, (size_t)i * 4, v);
    }
}

// ---------------------------------------------------------------------------
// Shared GEMM body (R7 proven config): 256 threads, 128 x 256 tile,
// warp 64 x 64, BK=64, 2-stage cp.async double buffer, bf16x3.
// OMODE: 1 bf16 hi/lo (+bias); 2 (acc+bias)*gate fp32.
// ---------------------------------------------------------------------------
template <int OMODE>
__device__ __forceinline__ void gemm_body(
        char* sm, int m0, int n0,
        const bf16* __restrict__ Ah, const bf16* __restrict__ Al,
        const bf16* __restrict__ Bh, const bf16* __restrict__ Bl,
        float* __restrict__ C, bf16* __restrict__ Ch, bf16* __restrict__ Cl,
        const float* __restrict__ bias,
        const float* __restrict__ t_emb, const float* __restrict__ ssg,
        int Kd, int lda, int ldb, int ldc) {
    constexpr int BN = 256;
    constexpr int APITCH = 72;
    constexpr int BPITCH = BN + 8;
    constexpr int ABYTES = 128 * APITCH * 2;
    constexpr int BBYTES = 64 * (BN + 8) * 2;
    constexpr int STAGE  = 2 * ABYTES + 2 * BBYTES;
    constexpr int WN     = BN / 64;

    const int tid  = threadIdx.x;
    const int warp = tid >> 5;
    const int lane = tid & 31;
    const int wm   = warp & 1;
    const int wn   = warp >> 1;

    wmma::fragment<wmma::accumulator, 16, 16, 16, float> acc[4][WN];
    #pragma unroll
    for (int i = 0; i < 4; i++)
        #pragma unroll
        for (int j = 0; j < WN; j++) wmma::fill_fragment(acc[i][j], 0.0f);

    auto load_stage = [&](int st, int k0) {
        char* base = sm + st * STAGE;
        bf16* dAh = (bf16*)base;
        bf16* dAl = (bf16*)(base + ABYTES);
        bf16* dBh = (bf16*)(base + 2 * ABYTES);
        bf16* dBl = (bf16*)(base + 2 * ABYTES + BBYTES);
        #pragma unroll
        for (int i = 0; i < 8; i++) {
            int idx = tid + (i << 8);
            int l = idx & 1023;
            int r = l >> 3, c = (l & 7) * 8;
            const bf16* src = (idx < 1024 ? Ah : Al) + (size_t)(m0 + r) * lda + k0 + c;
            cp_async16((idx < 1024 ? dAh : dAl) + r * APITCH + c, src);
        }
        constexpr int CPR = BN / 8;
        #pragma unroll
        for (int i = 0; i < BN / 16; i++) {
            int idx = tid + (i << 8);
            int l = idx & (8 * BN - 1);
            int r = l / CPR, c = (l % CPR) * 8;
            const bf16* src = (idx < 8 * BN ? Bh : Bl) + (size_t)(k0 + r) * ldb + n0 + c;
            cp_async16((idx < 8 * BN ? dBh : dBl) + r * BPITCH + c, src);
        }
    };

    const int nIter = Kd >> 6;
    load_stage(0, 0); cp_commit();
    if (nIter > 1) { load_stage(1, 64); cp_commit(); }

    for (int it = 0; it < nIter; ++it) {
        if (it + 1 < nIter) cp_wait1(); else cp_wait0();
        __syncthreads();

        char* base = sm + (it & 1) * STAGE;
        const bf16* sAh = (const bf16*)base;
        const bf16* sAl = (const bf16*)(base + ABYTES);
        const bf16* sBh = (const bf16*)(base + 2 * ABYTES);
        const bf16* sBl = (const bf16*)(base + 2 * ABYTES + BBYTES);
        #pragma unroll
        for (int kk = 0; kk < 4; kk++) {
            wmma::fragment<wmma::matrix_a, 16, 16, 16, bf16, wmma::row_major> ah[4], al[4];
            #pragma unroll
            for (int i = 0; i < 4; i++) {
                wmma::load_matrix_sync(ah[i], sAh + (wm * 64 + 16 * i) * APITCH + kk * 16, APITCH);
                wmma::load_matrix_sync(al[i], sAl + (wm * 64 + 16 * i) * APITCH + kk * 16, APITCH);
            }
            #pragma unroll
            for (int j = 0; j < WN; j++) {
                const int ncol = wn * (BN / 4) + 16 * j;
                wmma::fragment<wmma::matrix_b, 16, 16, 16, bf16, wmma::row_major> bh, bl;
                wmma::load_matrix_sync(bh, sBh + (kk * 16) * BPITCH + ncol, BPITCH);
                wmma::load_matrix_sync(bl, sBl + (kk * 16) * BPITCH + ncol, BPITCH);
                #pragma unroll
                for (int i = 0; i < 4; i++) wmma::mma_sync(acc[i][j], ah[i], bh, acc[i][j]);
                #pragma unroll
                for (int i = 0; i < 4; i++) wmma::mma_sync(acc[i][j], al[i], bh, acc[i][j]);
                #pragma unroll
                for (int i = 0; i < 4; i++) wmma::mma_sync(acc[i][j], ah[i], bl, acc[i][j]);
            }
        }

        if (it + 2 < nIter) {
            __syncthreads();
            load_stage(it & 1, (it + 2) << 6);
            cp_commit();
        }
    }

    __syncthreads();
    float* stag = (float*)sm + warp * 2560;  // 64 x 40 floats per warp
    const int bidx = m0 / Lc;
    #pragma unroll
    for (int p = 0; p < WN / 2; p++) {
        #pragma unroll
        for (int i = 0; i < 4; i++)
            #pragma unroll
            for (int jj = 0; jj < 2; jj++)
                wmma::store_matrix_sync(stag + (16 * i) * 40 + 16 * jj,
                                        acc[i][2 * p + jj], 40, wmma::mem_row_major);
        __syncwarp();
        #pragma unroll
        for (int itr = 0; itr < 16; itr++) {
            int g = lane + itr * 32;
            int r = g >> 3;
            int c = (g & 7) * 4;
            float4 v = *reinterpret_cast<const float4*>(stag + r * 40 + c);
            int gr = m0 + wm * 64 + r;
            int gc = n0 + wn * (BN / 4) + p * 32 + c;
            if constexpr (OMODE == 1) {
                if (bias) {
                    float4 bv = *reinterpret_cast<const float4*>(&bias[gc]);
                    v.x += bv.x; v.y += bv.y; v.z += bv.z; v.w += bv.w;
                }
                split_store4(Ch, Cl, (size_t)gr * ldc + gc, v);
            } else {
                float4 bv = *reinterpret_cast<const float4*>(&bias[gc]);
                float4 g1 = *reinterpret_cast<const float4*>(&t_emb[(size_t)(bidx * 3 + 2) * Dc + gc]);
                float4 g2 = *reinterpret_cast<const float4*>(&ssg[2 * Dc + gc]);
                float4 o;
                o.x = (v.x + bv.x) * (g1.x + g2.x);
                o.y = (v.y + bv.y) * (g1.y + g2.y);
                o.z = (v.z + bv.z) * (g1.z + g2.z);
                o.w = (v.w + bv.w) * (g1.w + g2.w);
                *reinterpret_cast<float4*>(&C[(size_t)gr * ldc + gc]) = o;
            }
        }
        __syncwarp();
    }
}

// ---------------------------------------------------------------------------
// Merged q+kv projection, 1-D packed grid of 640 CTAs:
//   bid < 512  -> kv tile:  x = bid & 15, y = bid >> 4  (k_lens M-skip)
//   bid >= 512 -> q tile:   r = bid-512, x = r & 7, y = r >> 3
// q tiles queue directly behind kv tiles and fill kv's dead/tail waves.
// ---------------------------------------------------------------------------
__global__ void __launch_bounds__(256)
gemm_qkv(const bf16* __restrict__ xk_h, const bf16* __restrict__ xk_l,
         const bf16* __restrict__ wkv_h, const bf16* __restrict__ wkv_l,
         bf16* __restrict__ kv_h, bf16* __restrict__ kv_l,
         const float* __restrict__ bkv,
         const bf16* __restrict__ lat_h, const bf16* __restrict__ lat_l,
         const bf16* __restrict__ wq_h, const bf16* __restrict__ wq_l,
         bf16* __restrict__ q_h, bf16* __restrict__ q_l,
         const float* __restrict__ bq,
         const int* __restrict__ k_lens) {
    extern __shared__ char sm[];
    const int bid = blockIdx.x;
    if (bid < 512) {
        const int m0 = (bid >> 4) * 128;
        const int bb = m0 >> 10;                        // m0 / Kc
        if (m0 - (bb << 10) >= k_lens[bb]) return;      // dead M tile
        gemm_body<1>(sm, m0, (bid & 15) * 256,
                     xk_h, xk_l, wkv_h, wkv_l,
                     nullptr, kv_h, kv_l, bkv, nullptr, nullptr,
                     KVc, KVc, 2 * Dc, 2 * Dc);
    } else {
        const int r = bid - 512;
        gemm_body<1>(sm, (r >> 3) * 128, (r & 7) * 256,
                     lat_h, lat_l, wq_h, wq_l,
                     nullptr, q_h, q_l, bq, nullptr, nullptr,
                     Dc, Dc, Dc, Dc);
    }
}

// ---------------------------------------------------------------------------
// Output projection: out = (at @ Wo + bo) * gate
// ---------------------------------------------------------------------------
__global__ void __launch_bounds__(256)
gemm_out(const bf16* __restrict__ Ah, const bf16* __restrict__ Al,
         const bf16* __restrict__ Bh, const bf16* __restrict__ Bl,
         float* __restrict__ C, const float* __restrict__ bias,
         const float* __restrict__ t_emb, const float* __restrict__ ssg) {
    extern __shared__ char sm[];
    gemm_body<2>(sm, blockIdx.y * 128, blockIdx.x * 256,
                 Ah, Al, Bh, Bl, C, nullptr, nullptr, bias, t_emb, ssg,
                 Dc, Dc, Dc, Dc);
}

// ---------------------------------------------------------------------------
// Fused flash attention: scores + (max-free) softmax + P·V + qmask.
// ---------------------------------------------------------------------------
constexpr int FL_QH = 0;        // Q hi  128 x 136 bf16   (34816)
constexpr int FL_QL = 34816;    // Q lo
constexpr int FL_KH = 69632;    // K hi   64 x 136 bf16   (17408)
constexpr int FL_KL = 87040;    // K lo
constexpr int FL_V0 = 104448;   // V stage: + st*34816 ; {hi, lo} 17408 each
constexpr int FL_S  = 174080;   // S fp32 [128][72] (36864); P hi/lo overlay
constexpr int FL_PH = 174080;   // P hi bf16 [128][72] (18432)
constexpr int FL_PL = 192512;   // P lo
constexpr int FL_RS = 210944;   // rowsum float[128]
constexpr int FL_SMEM = 211456;

__global__ void __launch_bounds__(256)
flash_kernel(const bf16* __restrict__ qh, const bf16* __restrict__ ql,
             const bf16* __restrict__ kvh, const bf16* __restrict__ kvl,
             bf16* __restrict__ ath, bf16* __restrict__ atl,
             const int* __restrict__ k_lens, const int* __restrict__ q_lens) {
    extern __shared__ char sm[];
    const int tid = threadIdx.x, warp = tid >> 5, lane = tid & 31;
    const int wm = warp & 1, wn = warp >> 1;
    const int z = blockIdx.z, b = z >> 4, h = z & 15;
    const int m0 = blockIdx.y * 128;
    const int klen = k_lens[b];
    const int qlen = q_lens[b];
    const int nb = (klen + 63) >> 6;
    const float alpha = 0.08838834764831845f;   // 1/sqrt(128)

    float* rowsum = (float*)(sm + FL_RS);
    if (tid < 128) rowsum[tid] = 0.0f;

    const bf16* qbh = qh + ((size_t)(b * Lc + m0) * Dc + h * Cc);
    const bf16* qbl = ql + ((size_t)(b * Lc + m0) * Dc + h * Cc);
    const bf16* kbh = kvh + ((size_t)b * Kc * 2 * Dc + h * Cc);
    const bf16* kbl = kvl + ((size_t)b * Kc * 2 * Dc + h * Cc);
    const bf16* vbh = kvh + ((size_t)b * Kc * 2 * Dc + Dc + h * Cc);
    const bf16* vbl = kvl + ((size_t)b * Kc * 2 * Dc + Dc + h * Cc);

    auto load_k = [&](int kb) {
        #pragma unroll
        for (int i = 0; i < 8; i++) {
            int idx = tid + (i << 8);
            int l = idx & 1023;
            int r = l >> 4, c = (l & 15) * 8;
            const bf16* src = (idx < 1024 ? kbh : kbl) + (size_t)(kb * 64 + r) * (2 * Dc) + c;
            char* dst = sm + (idx < 1024 ? FL_KH : FL_KL);
            cp_async16(dst + r * 272 + c * 2, src);
        }
    };
    auto load_v = [&](int kb) {
        char* vb = sm + FL_V0 + (kb & 1) * 34816;
        #pragma unroll
        for (int i = 0; i < 8; i++) {
            int idx = tid + (i << 8);
            int l = idx & 1023;
            int r = l >> 4, c = (l & 15) * 8;
            const bf16* src = (idx < 1024 ? vbh : vbl) + (size_t)(kb * 64 + r) * (2 * Dc) + c;
            cp_async16(vb + (idx < 1024 ? 0 : 17408) + r * 272 + c * 2, src);
        }
    };

    // prologue: Q (one group), K0, V0
    #pragma unroll
    for (int i = 0; i < 16; i++) {
        int idx = tid + (i << 8);
        int l = idx & 2047;
        int r = l >> 4, c = (l & 15) * 8;
        const bf16* src = (idx < 2048 ? qbh : qbl) + (size_t)r * Dc + c;
        char* dst = sm + (idx < 2048 ? FL_QH : FL_QL);
        cp_async16(dst + r * 272 + c * 2, src);
    }
    cp_commit();
    load_k(0); cp_commit();
    load_v(0); cp_commit();

    const bf16* sQh = (const bf16*)(sm + FL_QH);
    const bf16* sQl = (const bf16*)(sm + FL_QL);
    const bf16* sKh = (const bf16*)(sm + FL_KH);
    const bf16* sKl = (const bf16*)(sm + FL_KL);
    float* Ssm = (float*)(sm + FL_S);
    bf16* Ph = (bf16*)(sm + FL_PH);
    bf16* Pl = (bf16*)(sm + FL_PL);

    wmma::fragment<wmma::accumulator, 16, 16, 16, float> oacc[4][2];
    #pragma unroll
    for (int i = 0; i < 4; i++)
        #pragma unroll
        for (int j = 0; j < 2; j++) wmma::fill_fragment(oacc[i][j], 0.0f);

    for (int kb = 0; kb < nb; ++kb) {
        cp_wait1();          // K(kb) (and Q) arrived
        __syncthreads();

        // ---- S = Q · K^T : warp tile 64(q) x 16(k), acc[4] ----
        {
            wmma::fragment<wmma::accumulator, 16, 16, 16, float> sacc[4];
            #pragma unroll
            for (int i = 0; i < 4; i++) wmma::fill_fragment(sacc[i], 0.0f);
            #pragma unroll
            for (int kk = 0; kk < 8; kk++) {
                wmma::fragment<wmma::matrix_a, 16, 16, 16, bf16, wmma::row_major> ah[4], al[4];
                #pragma unroll
                for (int i = 0; i < 4; i++) {
                    wmma::load_matrix_sync(ah[i], sQh + (wm * 64 + 16 * i) * 136 + kk * 16, 136);
                    wmma::load_matrix_sync(al[i], sQl + (wm * 64 + 16 * i) * 136 + kk * 16, 136);
                }
                wmma::fragment<wmma::matrix_b, 16, 16, 16, bf16, wmma::col_major> bh, bl;
                wmma::load_matrix_sync(bh, sKh + (wn * 16) * 136 + kk * 16, 136);
                wmma::load_matrix_sync(bl, sKl + (wn * 16) * 136 + kk * 16, 136);
                #pragma unroll
                for (int i = 0; i < 4; i++) wmma::mma_sync(sacc[i], ah[i], bh, sacc[i]);
                #pragma unroll
                for (int i = 0; i < 4; i++) wmma::mma_sync(sacc[i], al[i], bh, sacc[i]);
                #pragma unroll
                for (int i = 0; i < 4; i++) wmma::mma_sync(sacc[i], ah[i], bl, sacc[i]);
            }
            #pragma unroll
            for (int i = 0; i < 4; i++)
                wmma::store_matrix_sync(Ssm + (wm * 64 + 16 * i) * 72 + wn * 16,
                                        sacc[i], 72, wmma::mem_row_major);
        }
        __syncthreads();

        // ---- exp (max-free) + P hi/lo + rowsum ----
        {
            const int row = tid >> 1, ch = (tid & 1) << 5;
            float e[32];
            #pragma unroll
            for (int c = 0; c < 32; c++) e[c] = Ssm[row * 72 + ch + c];
            __syncthreads();     // all reads done before P overwrites S
            float ps = 0.0f;
            const int kc0 = kb * 64 + ch;
            #pragma unroll
            for (int c = 0; c < 32; c++) {
                float v = (kc0 + c < klen) ? expf(e[c] * alpha) : 0.0f;
                ps += v;
                bf16 hi = __float2bfloat16(v);
                Ph[row * 72 + ch + c] = hi;
                Pl[row * 72 + ch + c] = __float2bfloat16(v - __bfloat162float(hi));
            }
            ps += __shfl_xor_sync(0xffffffffu, ps, 1);
            if ((tid & 1) == 0) rowsum[row] += ps;
        }

        const bool more = (kb + 1 < nb);
        if (more) { load_k(kb + 1); cp_commit(); load_v(kb + 1); cp_commit(); }
        if (more) cp_wait2(); else cp_wait0();   // V(kb) arrived
        __syncthreads();                          // P + V visible

        // ---- O += P · V : warp tile 64(q) x 32(c), acc[4][2] ----
        {
            const bf16* sVh = (const bf16*)(sm + FL_V0 + (kb & 1) * 34816);
            const bf16* sVl = (const bf16*)(sm + FL_V0 + (kb & 1) * 34816 + 17408);
            #pragma unroll
            for (int kk = 0; kk < 4; kk++) {
                wmma::fragment<wmma::matrix_a, 16, 16, 16, bf16, wmma::row_major> ah[4], al[4];
                #pragma unroll
                for (int i = 0; i < 4; i++) {
                    wmma::load_matrix_sync(ah[i], Ph + (wm * 64 + 16 * i) * 72 + kk * 16, 72);
                    wmma::load_matrix_sync(al[i], Pl + (wm * 64 + 16 * i) * 72 + kk * 16, 72);
                }
                #pragma unroll
                for (int j = 0; j < 2; j++) {
                    const int ncol = wn * 32 + 16 * j;
                    wmma::fragment<wmma::matrix_b, 16, 16, 16, bf16, wmma::row_major> bh, bl;
                    wmma::load_matrix_sync(bh, sVh + (kk * 16) * 136 + ncol, 136);
                    wmma::load_matrix_sync(bl, sVl + (kk * 16) * 136 + ncol, 136);
                    #pragma unroll
                    for (int i = 0; i < 4; i++) wmma::mma_sync(oacc[i][j], ah[i], bh, oacc[i][j]);
                    #pragma unroll
                    for (int i = 0; i < 4; i++) wmma::mma_sync(oacc[i][j], al[i], bh, oacc[i][j]);
                    #pragma unroll
                    for (int i = 0; i < 4; i++) wmma::mma_sync(oacc[i][j], ah[i], bl, oacc[i][j]);
                }
            }
        }
    }

    // ---- epilogue: scale by 1/rowsum, apply q_lens mask, store bf16 hi/lo ----
    __syncthreads();
    float* stag = (float*)sm + warp * 2560;   // safely inside [0, 81920) = Q/K region
    #pragma unroll
    for (int i = 0; i < 4; i++)
        #pragma unroll
        for (int j = 0; j < 2; j++)
            wmma::store_matrix_sync(stag + (16 * i) * 40 + 16 * j, oacc[i][j], 40,
                                    wmma::mem_row_major);
    __syncwarp();
    #pragma unroll
    for (int itr = 0; itr < 16; itr++) {
        int g = lane + itr * 32;
        int r = g >> 3;
        int c = (g & 7) * 4;
        float4 v = *reinterpret_cast<const float4*>(stag + r * 40 + c);
        int lrow = wm * 64 + r;
        int gc = wn * 32 + c;
        float rinv = (m0 + lrow < qlen) ? (1.0f / rowsum[lrow]) : 0.0f;
        v.x *= rinv; v.y *= rinv; v.z *= rinv; v.w *= rinv;
        split_store4(ath, atl, (size_t)(b * Lc + m0 + lrow) * Dc + h * Cc + gc, v);
    }
}

// ---------------------------------------------------------------------------
// LayerNorm of x -> xk hi/lo (rows >= k_lens[b] skipped: never consumed)
// ---------------------------------------------------------------------------
__global__ void ln_x_kernel(const float* __restrict__ x,
                            const float* __restrict__ w,
                            const float* __restrict__ b,
                            bf16* __restrict__ out_hi, bf16* __restrict__ out_lo,
                            const int* __restrict__ k_lens) {
    __shared__ float red[33];
    const int row = blockIdx.x;
    const int bidx = row >> 10;                   // row / Kc
    if ((row & (Kc - 1)) >= k_lens[bidx]) return; // dead row
    const size_t base = (size_t)row * KVc;
    const int t = threadIdx.x;
    const int c0 = t * 4, c1 = c0 + 1024;

    float4 v0 = *reinterpret_cast<const float4*>(&x[base + c0]);
    float4 v1 = *reinterpret_cast<const float4*>(&x[base + c1]);
    float s = v0.x + v0.y + v0.z + v0.w + v1.x + v1.y + v1.z + v1.w;
    float mean = block_sum256(s, red) * (1.0f / KVc);
    float d0x = v0.x - mean, d0y = v0.y - mean, d0z = v0.z - mean, d0w = v0.w - mean;
    float d1x = v1.x - mean, d1y = v1.y - mean, d1z = v1.z - mean, d1w = v1.w - mean;
    float sq = d0x*d0x + d0y*d0y + d0z*d0z + d0w*d0w + d1x*d1x + d1y*d1y + d1z*d1z + d1w*d1w;
    float var = block_sum256(sq, red) * (1.0f / KVc);
    float rstd = rsqrtf(var + 1e-5f);

    float4 w0 = *reinterpret_cast<const float4*>(&w[c0]);
    float4 w1 = *reinterpret_cast<const float4*>(&w[c1]);
    float4 b0 = *reinterpret_cast<const float4*>(&b[c0]);
    float4 b1 = *reinterpret_cast<const float4*>(&b[c1]);
    split_store4(out_hi, out_lo, base + c0,
        make_float4(d0x*rstd*w0.x + b0.x, d0y*rstd*w0.y + b0.y,
                    d0z*rstd*w0.z + b0.z, d0w*rstd*w0.w + b0.w));
    split_store4(out_hi, out_lo, base + c1,
        make_float4(d1x*rstd*w1.x + b1.x, d1y*rstd*w1.y + b1.y,
                    d1z*rstd*w1.z + b1.z, d1w*rstd*w1.w + b1.w));
}

// ---------------------------------------------------------------------------
// LayerNorm of latents + adaLN modulation -> lat hi/lo
// ---------------------------------------------------------------------------
__global__ void ln_lat_kernel(const float* __restrict__ latents,
                              const float* __restrict__ t_emb,
                              const float* __restrict__ ssg,
                              bf16* __restrict__ out_hi, bf16* __restrict__ out_lo) {
    __shared__ float red[33];
    const int row = blockIdx.x;
    const int bidx = row / Lc;
    const size_t base = (size_t)row * Dc;
    const int t = threadIdx.x;
    const int c0 = t * 4, c1 = c0 + 1024;

    float4 v0 = *reinterpret_cast<const float4*>(&latents[base + c0]);
    float4 v1 = *reinterpret_cast<const float4*>(&latents[base + c1]);
    float s = v0.x + v0.y + v0.z + v0.w + v1.x + v1.y + v1.z + v1.w;
    float mean = block_sum256(s, red) * (1.0f / Dc);
    float d0x = v0.x - mean, d0y = v0.y - mean, d0z = v0.z - mean, d0w = v0.w - mean;
    float d1x = v1.x - mean, d1y = v1.y - mean, d1z = v1.z - mean, d1w = v1.w - mean;
    float sq = d0x*d0x + d0y*d0y + d0z*d0z + d0w*d0w + d1x*d1x + d1y*d1y + d1z*d1z + d1w*d1w;
    float var = block_sum256(sq, red) * (1.0f / Dc);
    float rstd = rsqrtf(var + 1e-5f);

    const float* sh_t = t_emb + (size_t)(bidx * 3 + 0) * Dc;
    const float* sc_t = t_emb + (size_t)(bidx * 3 + 1) * Dc;

    #pragma unroll
    for (int half = 0; half < 2; half++) {
        int c = (half == 0) ? c0 : c1;
        float dv[4] = { (half ? d1x : d0x), (half ? d1y : d0y),
                        (half ? d1z : d0z), (half ? d1w : d0w) };
        float4 sht = *reinterpret_cast<const float4*>(&sh_t[c]);
        float4 sct = *reinterpret_cast<const float4*>(&sc_t[c]);
        float4 shs = *reinterpret_cast<const float4*>(&ssg[c]);
        float4 scs = *reinterpret_cast<const float4*>(&ssg[Dc + c]);
        float4 o;
        o.x = dv[0]*rstd * (1.0f + sct.x + scs.x) + sht.x + shs.x;
        o.y = dv[1]*rstd * (1.0f + sct.y + scs.y) + sht.y + shs.y;
        o.z = dv[2]*rstd * (1.0f + sct.z + scs.z) + sht.z + shs.z;
        o.w = dv[3]*rstd * (1.0f + sct.w + scs.w) + sht.w + shs.w;
        split_store4(out_hi, out_lo, base + c, o);
    }
}

// ---------------------------------------------------------------------------
// Launch — critical path: s0 = split_Wkv -> ln_x -> (wait q deps) gemm_qkv ->
// flash -> (wait Wo) gemm_out. Side stream: split_Wq -> ln_lat (evB), then
// split_Wo (evC) overlapping the merged GEMM.
// ---------------------------------------------------------------------------
extern "C" void kernel_launch(void* const* d_in, const int* in_sizes, int n_in,
                              void* d_out, int out_size) {
    (void)in_sizes; (void)n_in; (void)out_size;
    const float* x       = (const float*)d_in[0];
    const float* latents = (const float*)d_in[1];
    const float* t_emb   = (const float*)d_in[2];
    const int*   q_lens  = (const int*)  d_in[3];
    const int*   k_lens  = (const int*)  d_in[4];
    const float* ln_kv_w = (const float*)d_in[5];
    const float* ln_kv_b = (const float*)d_in[6];
    const float* ssg     = (const float*)d_in[7];
    const float* Wq      = (const float*)d_in[8];
    const float* bq      = (const float*)d_in[9];
    const float* Wkv     = (const float*)d_in[10];
    const float* bkv     = (const float*)d_in[11];
    const float* Wo      = (const float*)d_in[12];
    const float* bo      = (const float*)d_in[13];
    float* out = (float*)d_out;

    bf16 *xk_h, *xk_l, *lat_h, *lat_l, *q_h, *q_l, *kv_h, *kv_l;
    bf16 *at_h, *at_l, *wq_h, *wq_l, *wkv_h, *wkv_l, *wo_h, *wo_l;
    cudaGetSymbolAddress((void**)&xk_h, g_xk_hi);   cudaGetSymbolAddress((void**)&xk_l, g_xk_lo);
    cudaGetSymbolAddress((void**)&lat_h, g_lat_hi); cudaGetSymbolAddress((void**)&lat_l, g_lat_lo);
    cudaGetSymbolAddress((void**)&q_h, g_q_hi);     cudaGetSymbolAddress((void**)&q_l, g_q_lo);
    cudaGetSymbolAddress((void**)&kv_h, g_kv_hi);   cudaGetSymbolAddress((void**)&kv_l, g_kv_lo);
    cudaGetSymbolAddress((void**)&at_h, g_at_hi);   cudaGetSymbolAddress((void**)&at_l, g_at_lo);
    cudaGetSymbolAddress((void**)&wq_h, g_wq_hi);   cudaGetSymbolAddress((void**)&wq_l, g_wq_lo);
    cudaGetSymbolAddress((void**)&wkv_h, g_wkv_hi); cudaGetSymbolAddress((void**)&wkv_l, g_wkv_lo);
    cudaGetSymbolAddress((void**)&wo_h, g_wo_hi);   cudaGetSymbolAddress((void**)&wo_l, g_wo_lo);

    constexpr int SMEM_F256 = 2 * (2 * 128 * 72 * 2 + 2 * 64 * 264 * 2);  // 208896
    cudaFuncSetAttribute(gemm_qkv, cudaFuncAttributeMaxDynamicSharedMemorySize, SMEM_F256);
    cudaFuncSetAttribute(gemm_out, cudaFuncAttributeMaxDynamicSharedMemorySize, SMEM_F256);
    cudaFuncSetAttribute(flash_kernel, cudaFuncAttributeMaxDynamicSharedMemorySize, FL_SMEM);

    // Side stream + events, created once on the first (non-captured) call.
    static cudaStream_t sB = nullptr;
    static cudaEvent_t evRoot = nullptr, evB = nullptr, evC = nullptr;
    if (sB == nullptr) {
        cudaStreamCreateWithFlags(&sB, cudaStreamNonBlocking);
        cudaEventCreateWithFlags(&evRoot, cudaEventDisableTiming);
        cudaEventCreateWithFlags(&evB, cudaEventDisableTiming);
        cudaEventCreateWithFlags(&evC, cudaEventDisableTiming);
    }
    cudaStream_t s0 = 0;

    // fork
    cudaEventRecord(evRoot, s0);
    cudaStreamWaitEvent(sB, evRoot, 0);

    // ---- side stream: q-tile inputs first (short), then Wo split ----
    split_kernel<<<2048, 256, 0, sB>>>(Wq, wq_h, wq_l, Dc * Dc / 4);
    ln_lat_kernel<<<Bc * Lc, 256, 0, sB>>>(latents, t_emb, ssg, lat_h, lat_l);
    cudaEventRecord(evB, sB);
    split_kernel<<<2048, 256, 0, sB>>>(Wo, wo_h, wo_l, Dc * Dc / 4);
    cudaEventRecord(evC, sB);

    // ---- main stream: kv-tile inputs (the longer pole) ----
    split_kernel<<<2048, 256, 0, s0>>>(Wkv, wkv_h, wkv_l, KVc * 2 * Dc / 4);
    ln_x_kernel<<<Bc * Kc, 256, 0, s0>>>(x, ln_kv_w, ln_kv_b, xk_h, xk_l, k_lens);

    // join: q-tile inputs ready (evB arrives well before this point is reached)
    cudaStreamWaitEvent(s0, evB, 0);

    // merged q + kv projection (1-D packed grid: 512 kv slots + 128 q tiles)
    gemm_qkv<<<640, 256, SMEM_F256, s0>>>(
        xk_h, xk_l, wkv_h, wkv_l, kv_h, kv_l, bkv,
        lat_h, lat_l, wq_h, wq_l, q_h, q_l, bq, k_lens);

    // fused attention
    flash_kernel<<<dim3(1, Lc / 128, Bc * Hc), 256, FL_SMEM, s0>>>(
        q_h, q_l, kv_h, kv_l, at_h, at_l, k_lens, q_lens);

    // out = (at @ Wo + bo) * gate  (Wo split finished long ago on sB)
    cudaStreamWaitEvent(s0, evC, 0);
    gemm_out<<<dim3(Dc / 256, (Bc * Lc) / 128, 1), 256, SMEM_F256, s0>>>(
        at_h, at_l, wo_h, wo_l, out, bo, t_emb, ssg);
}

// round 16
// speedup vs baseline: 1.0322x; 1.0322x over previous
#include <cuda_runtime.h>
#include <cuda_bf16.h>
#include <mma.h>
#include <cstdint>

using namespace nvcuda;
typedef __nv_bfloat16 bf16;

// Problem dims
constexpr int Bc  = 4;
constexpr int Lc  = 512;
constexpr int Dc  = 2048;
constexpr int Hc  = 16;
constexpr int Cc  = 128;
constexpr int KVc = 2048;
constexpr int Kc  = 1024;   // T*LA

// ---------------------------------------------------------------------------
// Scratch (device globals — allocation-free rule)
// ---------------------------------------------------------------------------
__device__ bf16  g_xk_hi[(size_t)Bc * Kc * KVc];
__device__ bf16  g_xk_lo[(size_t)Bc * Kc * KVc];
__device__ bf16  g_lat_hi[(size_t)Bc * Lc * Dc];
__device__ bf16  g_lat_lo[(size_t)Bc * Lc * Dc];
__device__ bf16  g_q_hi[(size_t)Bc * Lc * Dc];
__device__ bf16  g_q_lo[(size_t)Bc * Lc * Dc];
__device__ bf16  g_kv_hi[(size_t)Bc * Kc * 2 * Dc];
__device__ bf16  g_kv_lo[(size_t)Bc * Kc * 2 * Dc];
__device__ bf16  g_at_hi[(size_t)Bc * Lc * Dc];
__device__ bf16  g_at_lo[(size_t)Bc * Lc * Dc];
__device__ bf16  g_wq_hi[(size_t)Dc * Dc];
__device__ bf16  g_wq_lo[(size_t)Dc * Dc];
__device__ bf16  g_wkv_hi[(size_t)KVc * 2 * Dc];
__device__ bf16  g_wkv_lo[(size_t)KVc * 2 * Dc];
__device__ bf16  g_wo_hi[(size_t)Dc * Dc];
__device__ bf16  g_wo_lo[(size_t)Dc * Dc];

// ---------------------------------------------------------------------------
// Helpers
// ---------------------------------------------------------------------------
__device__ __forceinline__ void cp_async16(void* smem_dst, const void* gmem_src) {
    unsigned s = (unsigned)__cvta_generic_to_shared(smem_dst);
    asm volatile("cp.async.cg.shared.global [%0], [%1], 16;\n" :: "r"(s), "l"(gmem_src));
}
__device__ __forceinline__ void cp_commit() { asm volatile("cp.async.commit_group;\n"); }
__device__ __forceinline__ void cp_wait0()  { asm volatile("cp.async.wait_group 0;\n"); }
__device__ __forceinline__ void cp_wait1()  { asm volatile("cp.async.wait_group 1;\n"); }
__device__ __forceinline__ void cp_wait2()  { asm volatile("cp.async.wait_group 2;\n"); }

struct __align__(8) bf4 { bf16 v[4]; };
__device__ __forceinline__ void split_store4(bf16* hi, bf16* lo, size_t off, float4 f) {
    bf4 H, L;
    float ff[4] = { f.x, f.y, f.z, f.w };
    #pragma unroll
    for (int e = 0; e < 4; e++) {
        bf16 h = __float2bfloat16(ff[e]);
        H.v[e] = h;
        L.v[e] = __float2bfloat16(ff[e] - __bfloat162float(h));
    }
    *reinterpret_cast<bf4*>(hi + off) = H;
    *reinterpret_cast<bf4*>(lo + off) = L;
}

__device__ __forceinline__ float warp_sum(float v) {
    #pragma unroll
    for (int o = 16; o > 0; o >>= 1) v += __shfl_xor_sync(0xffffffffu, v, o);
    return v;
}
__device__ __forceinline__ float block_sum256(float v, float* red) {
    int lane = threadIdx.x & 31, w = threadIdx.x >> 5;
    v = warp_sum(v);
    if (lane == 0) red[w] = v;
    __syncthreads();
    if (w == 0) {
        float t = (lane < 8) ? red[lane] : 0.0f;
        t = warp_sum(t);
        if (lane == 0) red[32] = t;
    }
    __syncthreads();
    float r = red[32];
    __syncthreads();
    return r;
}

// ---------------------------------------------------------------------------
// fp32 -> bf16 hi/lo splitter (weights)
// ---------------------------------------------------------------------------
__global__ void split_kernel(const float* __restrict__ W,
                             bf16* __restrict__ hi, bf16* __restrict__ lo,
                             int total4) {
    int i = blockIdx.x * blockDim.x + threadIdx.x;
    const int stride = gridDim.x * blockDim.x;
    for (; i < total4; i += stride) {
        float4 v = reinterpret_cast<const float4*>(W)[i];
        split_store4(hi, lo, (size_t)i * 4, v);
    }
}

// ---------------------------------------------------------------------------
// bf16x3 GEMM (R7 proven config): 256 threads, 128 x BN tile, warp 64 x BN/4,
// BK=64, 2-stage cp.async double buffer.
// OMODE: 1 bf16 hi/lo (+bias); 2 (acc+bias)*gate fp32.
// mklens/rpb: optional M-tile skip (rows never consumed downstream).
// ---------------------------------------------------------------------------
template <int BN, int OMODE>
__global__ void __launch_bounds__(256)
gemm_ks(const bf16* __restrict__ Ah, const bf16* __restrict__ Al,
        const bf16* __restrict__ Bh, const bf16* __restrict__ Bl,
        float* __restrict__ C, bf16* __restrict__ Ch, bf16* __restrict__ Cl,
        const float* __restrict__ bias,
        const float* __restrict__ t_emb, const float* __restrict__ ssg,
        const int* __restrict__ mklens, int rpb,
        int Kd, int lda, int ldb, int ldc) {
    extern __shared__ char sm[];
    constexpr int APITCH = 72;                       // bf16 pitch, BK=64 (+8 pad)
    constexpr int BPITCH = BN + 8;
    constexpr int ABYTES = 128 * APITCH * 2;         // 18432 per A slice
    constexpr int BBYTES = 64 * (BN + 8) * 2;
    constexpr int STAGE  = 2 * ABYTES + 2 * BBYTES;
    constexpr int WN     = BN / 64;                  // wmma j-tiles per warp

    const int n0 = blockIdx.x * BN;
    const int m0 = blockIdx.y * 128;

    if (mklens) {
        const int bb2 = m0 / rpb;
        if (m0 - bb2 * rpb >= mklens[bb2]) return;   // dead M tile
    }

    const int tid  = threadIdx.x;
    const int warp = tid >> 5;
    const int lane = tid & 31;
    const int wm   = warp & 1;
    const int wn   = warp >> 1;

    wmma::fragment<wmma::accumulator, 16, 16, 16, float> acc[4][WN];
    #pragma unroll
    for (int i = 0; i < 4; i++)
        #pragma unroll
        for (int j = 0; j < WN; j++) wmma::fill_fragment(acc[i][j], 0.0f);

    auto load_stage = [&](int st, int k0) {
        char* base = sm + st * STAGE;
        bf16* dAh = (bf16*)base;
        bf16* dAl = (bf16*)(base + ABYTES);
        bf16* dBh = (bf16*)(base + 2 * ABYTES);
        bf16* dBl = (bf16*)(base + 2 * ABYTES + BBYTES);
        #pragma unroll
        for (int i = 0; i < 8; i++) {
            int idx = tid + (i << 8);
            int l = idx & 1023;
            int r = l >> 3, c = (l & 7) * 8;
            const bf16* src = (idx < 1024 ? Ah : Al) + (size_t)(m0 + r) * lda + k0 + c;
            cp_async16((idx < 1024 ? dAh : dAl) + r * APITCH + c, src);
        }
        constexpr int CPR = BN / 8;
        #pragma unroll
        for (int i = 0; i < BN / 16; i++) {
            int idx = tid + (i << 8);
            int l = idx & (8 * BN - 1);
            int r = l / CPR, c = (l % CPR) * 8;
            const bf16* src = (idx < 8 * BN ? Bh : Bl) + (size_t)(k0 + r) * ldb + n0 + c;
            cp_async16((idx < 8 * BN ? dBh : dBl) + r * BPITCH + c, src);
        }
    };

    const int nIter = Kd >> 6;
    load_stage(0, 0); cp_commit();
    if (nIter > 1) { load_stage(1, 64); cp_commit(); }

    for (int it = 0; it < nIter; ++it) {
        if (it + 1 < nIter) cp_wait1(); else cp_wait0();
        __syncthreads();

        char* base = sm + (it & 1) * STAGE;
        const bf16* sAh = (const bf16*)base;
        const bf16* sAl = (const bf16*)(base + ABYTES);
        const bf16* sBh = (const bf16*)(base + 2 * ABYTES);
        const bf16* sBl = (const bf16*)(base + 2 * ABYTES + BBYTES);
        #pragma unroll
        for (int kk = 0; kk < 4; kk++) {
            wmma::fragment<wmma::matrix_a, 16, 16, 16, bf16, wmma::row_major> ah[4], al[4];
            #pragma unroll
            for (int i = 0; i < 4; i++) {
                wmma::load_matrix_sync(ah[i], sAh + (wm * 64 + 16 * i) * APITCH + kk * 16, APITCH);
                wmma::load_matrix_sync(al[i], sAl + (wm * 64 + 16 * i) * APITCH + kk * 16, APITCH);
            }
            #pragma unroll
            for (int j = 0; j < WN; j++) {
                const int ncol = wn * (BN / 4) + 16 * j;
                wmma::fragment<wmma::matrix_b, 16, 16, 16, bf16, wmma::row_major> bh, bl;
                wmma::load_matrix_sync(bh, sBh + (kk * 16) * BPITCH + ncol, BPITCH);
                wmma::load_matrix_sync(bl, sBl + (kk * 16) * BPITCH + ncol, BPITCH);
                #pragma unroll
                for (int i = 0; i < 4; i++) wmma::mma_sync(acc[i][j], ah[i], bh, acc[i][j]);
                #pragma unroll
                for (int i = 0; i < 4; i++) wmma::mma_sync(acc[i][j], al[i], bh, acc[i][j]);
                #pragma unroll
                for (int i = 0; i < 4; i++) wmma::mma_sync(acc[i][j], ah[i], bl, acc[i][j]);
            }
        }

        if (it + 2 < nIter) {
            __syncthreads();
            load_stage(it & 1, (it + 2) << 6);
            cp_commit();
        }
    }

    __syncthreads();
    float* stag = (float*)sm + warp * 2560;  // 64 x 40 floats per warp
    const int bidx = m0 / Lc;
    #pragma unroll
    for (int p = 0; p < WN / 2; p++) {
        #pragma unroll
        for (int i = 0; i < 4; i++)
            #pragma unroll
            for (int jj = 0; jj < 2; jj++)
                wmma::store_matrix_sync(stag + (16 * i) * 40 + 16 * jj,
                                        acc[i][2 * p + jj], 40, wmma::mem_row_major);
        __syncwarp();
        #pragma unroll
        for (int itr = 0; itr < 16; itr++) {
            int g = lane + itr * 32;
            int r = g >> 3;
            int c = (g & 7) * 4;
            float4 v = *reinterpret_cast<const float4*>(stag + r * 40 + c);
            int gr = m0 + wm * 64 + r;
            int gc = n0 + wn * (BN / 4) + p * 32 + c;
            if constexpr (OMODE == 1) {
                if (bias) {
                    float4 bv = *reinterpret_cast<const float4*>(&bias[gc]);
                    v.x += bv.x; v.y += bv.y; v.z += bv.z; v.w += bv.w;
                }
                split_store4(Ch, Cl, (size_t)gr * ldc + gc, v);
            } else {
                float4 bv = *reinterpret_cast<const float4*>(&bias[gc]);
                float4 g1 = *reinterpret_cast<const float4*>(&t_emb[(size_t)(bidx * 3 + 2) * Dc + gc]);
                float4 g2 = *reinterpret_cast<const float4*>(&ssg[2 * Dc + gc]);
                float4 o;
                o.x = (v.x + bv.x) * (g1.x + g2.x);
                o.y = (v.y + bv.y) * (g1.y + g2.y);
                o.z = (v.z + bv.z) * (g1.z + g2.z);
                o.w = (v.w + bv.w) * (g1.w + g2.w);
                *reinterpret_cast<float4*>(&C[(size_t)gr * ldc + gc]) = o;
            }
        }
        __syncwarp();
    }
}

// ---------------------------------------------------------------------------
// Fused flash attention: scores + (max-free) softmax + P·V + qmask.
// ---------------------------------------------------------------------------
constexpr int FL_QH = 0;        // Q hi  128 x 136 bf16   (34816)
constexpr int FL_QL = 34816;    // Q lo
constexpr int FL_KH = 69632;    // K hi   64 x 136 bf16   (17408)
constexpr int FL_KL = 87040;    // K lo
constexpr int FL_V0 = 104448;   // V stage: + st*34816 ; {hi, lo} 17408 each
constexpr int FL_S  = 174080;   // S fp32 [128][72] (36864); P hi/lo overlay
constexpr int FL_PH = 174080;   // P hi bf16 [128][72] (18432)
constexpr int FL_PL = 192512;   // P lo
constexpr int FL_RS = 210944;   // rowsum float[128]
constexpr int FL_SMEM = 211456;

__global__ void __launch_bounds__(256)
flash_kernel(const bf16* __restrict__ qh, const bf16* __restrict__ ql,
             const bf16* __restrict__ kvh, const bf16* __restrict__ kvl,
             bf16* __restrict__ ath, bf16* __restrict__ atl,
             const int* __restrict__ k_lens, const int* __restrict__ q_lens) {
    extern __shared__ char sm[];
    const int tid = threadIdx.x, warp = tid >> 5, lane = tid & 31;
    const int wm = warp & 1, wn = warp >> 1;
    const int z = blockIdx.z, b = z >> 4, h = z & 15;
    const int m0 = blockIdx.y * 128;
    const int klen = k_lens[b];
    const int qlen = q_lens[b];
    const int nb = (klen + 63) >> 6;
    const float alpha = 0.08838834764831845f;   // 1/sqrt(128)

    float* rowsum = (float*)(sm + FL_RS);
    if (tid < 128) rowsum[tid] = 0.0f;

    const bf16* qbh = qh + ((size_t)(b * Lc + m0) * Dc + h * Cc);
    const bf16* qbl = ql + ((size_t)(b * Lc + m0) * Dc + h * Cc);
    const bf16* kbh = kvh + ((size_t)b * Kc * 2 * Dc + h * Cc);
    const bf16* kbl = kvl + ((size_t)b * Kc * 2 * Dc + h * Cc);
    const bf16* vbh = kvh + ((size_t)b * Kc * 2 * Dc + Dc + h * Cc);
    const bf16* vbl = kvl + ((size_t)b * Kc * 2 * Dc + Dc + h * Cc);

    auto load_k = [&](int kb) {
        #pragma unroll
        for (int i = 0; i < 8; i++) {
            int idx = tid + (i << 8);
            int l = idx & 1023;
            int r = l >> 4, c = (l & 15) * 8;
            const bf16* src = (idx < 1024 ? kbh : kbl) + (size_t)(kb * 64 + r) * (2 * Dc) + c;
            char* dst = sm + (idx < 1024 ? FL_KH : FL_KL);
            cp_async16(dst + r * 272 + c * 2, src);
        }
    };
    auto load_v = [&](int kb) {
        char* vb = sm + FL_V0 + (kb & 1) * 34816;
        #pragma unroll
        for (int i = 0; i < 8; i++) {
            int idx = tid + (i << 8);
            int l = idx & 1023;
            int r = l >> 4, c = (l & 15) * 8;
            const bf16* src = (idx < 1024 ? vbh : vbl) + (size_t)(kb * 64 + r) * (2 * Dc) + c;
            cp_async16(vb + (idx < 1024 ? 0 : 17408) + r * 272 + c * 2, src);
        }
    };

    // prologue: Q (one group), K0, V0
    #pragma unroll
    for (int i = 0; i < 16; i++) {
        int idx = tid + (i << 8);
        int l = idx & 2047;
        int r = l >> 4, c = (l & 15) * 8;
        const bf16* src = (idx < 2048 ? qbh : qbl) + (size_t)r * Dc + c;
        char* dst = sm + (idx < 2048 ? FL_QH : FL_QL);
        cp_async16(dst + r * 272 + c * 2, src);
    }
    cp_commit();
    load_k(0); cp_commit();
    load_v(0); cp_commit();

    const bf16* sQh = (const bf16*)(sm + FL_QH);
    const bf16* sQl = (const bf16*)(sm + FL_QL);
    const bf16* sKh = (const bf16*)(sm + FL_KH);
    const bf16* sKl = (const bf16*)(sm + FL_KL);
    float* Ssm = (float*)(sm + FL_S);
    bf16* Ph = (bf16*)(sm + FL_PH);
    bf16* Pl = (bf16*)(sm + FL_PL);

    wmma::fragment<wmma::accumulator, 16, 16, 16, float> oacc[4][2];
    #pragma unroll
    for (int i = 0; i < 4; i++)
        #pragma unroll
        for (int j = 0; j < 2; j++) wmma::fill_fragment(oacc[i][j], 0.0f);

    for (int kb = 0; kb < nb; ++kb) {
        cp_wait1();          // K(kb) (and Q) arrived
        __syncthreads();

        // ---- S = Q · K^T : warp tile 64(q) x 16(k), acc[4] ----
        {
            wmma::fragment<wmma::accumulator, 16, 16, 16, float> sacc[4];
            #pragma unroll
            for (int i = 0; i < 4; i++) wmma::fill_fragment(sacc[i], 0.0f);
            #pragma unroll
            for (int kk = 0; kk < 8; kk++) {
                wmma::fragment<wmma::matrix_a, 16, 16, 16, bf16, wmma::row_major> ah[4], al[4];
                #pragma unroll
                for (int i = 0; i < 4; i++) {
                    wmma::load_matrix_sync(ah[i], sQh + (wm * 64 + 16 * i) * 136 + kk * 16, 136);
                    wmma::load_matrix_sync(al[i], sQl + (wm * 64 + 16 * i) * 136 + kk * 16, 136);
                }
                wmma::fragment<wmma::matrix_b, 16, 16, 16, bf16, wmma::col_major> bh, bl;
                wmma::load_matrix_sync(bh, sKh + (wn * 16) * 136 + kk * 16, 136);
                wmma::load_matrix_sync(bl, sKl + (wn * 16) * 136 + kk * 16, 136);
                #pragma unroll
                for (int i = 0; i < 4; i++) wmma::mma_sync(sacc[i], ah[i], bh, sacc[i]);
                #pragma unroll
                for (int i = 0; i < 4; i++) wmma::mma_sync(sacc[i], al[i], bh, sacc[i]);
                #pragma unroll
                for (int i = 0; i < 4; i++) wmma::mma_sync(sacc[i], ah[i], bl, sacc[i]);
            }
            #pragma unroll
            for (int i = 0; i < 4; i++)
                wmma::store_matrix_sync(Ssm + (wm * 64 + 16 * i) * 72 + wn * 16,
                                        sacc[i], 72, wmma::mem_row_major);
        }
        __syncthreads();

        // ---- exp (max-free) + P hi/lo + rowsum ----
        {
            const int row = tid >> 1, ch = (tid & 1) << 5;
            float e[32];
            #pragma unroll
            for (int c = 0; c < 32; c++) e[c] = Ssm[row * 72 + ch + c];
            __syncthreads();     // all reads done before P overwrites S
            float ps = 0.0f;
            const int kc0 = kb * 64 + ch;
            #pragma unroll
            for (int c = 0; c < 32; c++) {
                float v = (kc0 + c < klen) ? expf(e[c] * alpha) : 0.0f;
                ps += v;
                bf16 hi = __float2bfloat16(v);
                Ph[row * 72 + ch + c] = hi;
                Pl[row * 72 + ch + c] = __float2bfloat16(v - __bfloat162float(hi));
            }
            ps += __shfl_xor_sync(0xffffffffu, ps, 1);
            if ((tid & 1) == 0) rowsum[row] += ps;
        }

        const bool more = (kb + 1 < nb);
        if (more) { load_k(kb + 1); cp_commit(); load_v(kb + 1); cp_commit(); }
        if (more) cp_wait2(); else cp_wait0();   // V(kb) arrived
        __syncthreads();                          // P + V visible

        // ---- O += P · V : warp tile 64(q) x 32(c), acc[4][2] ----
        {
            const bf16* sVh = (const bf16*)(sm + FL_V0 + (kb & 1) * 34816);
            const bf16* sVl = (const bf16*)(sm + FL_V0 + (kb & 1) * 34816 + 17408);
            #pragma unroll
            for (int kk = 0; kk < 4; kk++) {
                wmma::fragment<wmma::matrix_a, 16, 16, 16, bf16, wmma::row_major> ah[4], al[4];
                #pragma unroll
                for (int i = 0; i < 4; i++) {
                    wmma::load_matrix_sync(ah[i], Ph + (wm * 64 + 16 * i) * 72 + kk * 16, 72);
                    wmma::load_matrix_sync(al[i], Pl + (wm * 64 + 16 * i) * 72 + kk * 16, 72);
                }
                #pragma unroll
                for (int j = 0; j < 2; j++) {
                    const int ncol = wn * 32 + 16 * j;
                    wmma::fragment<wmma::matrix_b, 16, 16, 16, bf16, wmma::row_major> bh, bl;
                    wmma::load_matrix_sync(bh, sVh + (kk * 16) * 136 + ncol, 136);
                    wmma::load_matrix_sync(bl, sVl + (kk * 16) * 136 + ncol, 136);
                    #pragma unroll
                    for (int i = 0; i < 4; i++) wmma::mma_sync(oacc[i][j], ah[i], bh, oacc[i][j]);
                    #pragma unroll
                    for (int i = 0; i < 4; i++) wmma::mma_sync(oacc[i][j], al[i], bh, oacc[i][j]);
                    #pragma unroll
                    for (int i = 0; i < 4; i++) wmma::mma_sync(oacc[i][j], ah[i], bl, oacc[i][j]);
                }
            }
        }
    }

    // ---- epilogue: scale by 1/rowsum, apply q_lens mask, store bf16 hi/lo ----
    __syncthreads();
    float* stag = (float*)sm + warp * 2560;   // safely inside [0, 81920) = Q/K region
    #pragma unroll
    for (int i = 0; i < 4; i++)
        #pragma unroll
        for (int j = 0; j < 2; j++)
            wmma::store_matrix_sync(stag + (16 * i) * 40 + 16 * j, oacc[i][j], 40,
                                    wmma::mem_row_major);
    __syncwarp();
    #pragma unroll
    for (int itr = 0; itr < 16; itr++) {
        int g = lane + itr * 32;
        int r = g >> 3;
        int c = (g & 7) * 4;
        float4 v = *reinterpret_cast<const float4*>(stag + r * 40 + c);
        int lrow = wm * 64 + r;
        int gc = wn * 32 + c;
        float rinv = (m0 + lrow < qlen) ? (1.0f / rowsum[lrow]) : 0.0f;
        v.x *= rinv; v.y *= rinv; v.z *= rinv; v.w *= rinv;
        split_store4(ath, atl, (size_t)(b * Lc + m0 + lrow) * Dc + h * Cc + gc, v);
    }
}

// ---------------------------------------------------------------------------
// LayerNorm of x -> xk hi/lo (rows >= k_lens[b] skipped: never consumed)
// ---------------------------------------------------------------------------
__global__ void ln_x_kernel(const float* __restrict__ x,
                            const float* __restrict__ w,
                            const float* __restrict__ b,
                            bf16* __restrict__ out_hi, bf16* __restrict__ out_lo,
                            const int* __restrict__ k_lens) {
    __shared__ float red[33];
    const int row = blockIdx.x;
    const int bidx = row >> 10;                   // row / Kc
    if ((row & (Kc - 1)) >= k_lens[bidx]) return; // dead row
    const size_t base = (size_t)row * KVc;
    const int t = threadIdx.x;
    const int c0 = t * 4, c1 = c0 + 1024;

    float4 v0 = *reinterpret_cast<const float4*>(&x[base + c0]);
    float4 v1 = *reinterpret_cast<const float4*>(&x[base + c1]);
    float s = v0.x + v0.y + v0.z + v0.w + v1.x + v1.y + v1.z + v1.w;
    float mean = block_sum256(s, red) * (1.0f / KVc);
    float d0x = v0.x - mean, d0y = v0.y - mean, d0z = v0.z - mean, d0w = v0.w - mean;
    float d1x = v1.x - mean, d1y = v1.y - mean, d1z = v1.z - mean, d1w = v1.w - mean;
    float sq = d0x*d0x + d0y*d0y + d0z*d0z + d0w*d0w + d1x*d1x + d1y*d1y + d1z*d1z + d1w*d1w;
    float var = block_sum256(sq, red) * (1.0f / KVc);
    float rstd = rsqrtf(var + 1e-5f);

    float4 w0 = *reinterpret_cast<const float4*>(&w[c0]);
    float4 w1 = *reinterpret_cast<const float4*>(&w[c1]);
    float4 b0 = *reinterpret_cast<const float4*>(&b[c0]);
    float4 b1 = *reinterpret_cast<const float4*>(&b[c1]);
    split_store4(out_hi, out_lo, base + c0,
        make_float4(d0x*rstd*w0.x + b0.x, d0y*rstd*w0.y + b0.y,
                    d0z*rstd*w0.z + b0.z, d0w*rstd*w0.w + b0.w));
    split_store4(out_hi, out_lo, base + c1,
        make_float4(d1x*rstd*w1.x + b1.x, d1y*rstd*w1.y + b1.y,
                    d1z*rstd*w1.z + b1.z, d1w*rstd*w1.w + b1.w));
}

// ---------------------------------------------------------------------------
// LayerNorm of latents + adaLN modulation -> lat hi/lo
// ---------------------------------------------------------------------------
__global__ void ln_lat_kernel(const float* __restrict__ latents,
                              const float* __restrict__ t_emb,
                              const float* __restrict__ ssg,
                              bf16* __restrict__ out_hi, bf16* __restrict__ out_lo) {
    __shared__ float red[33];
    const int row = blockIdx.x;
    const int bidx = row / Lc;
    const size_t base = (size_t)row * Dc;
    const int t = threadIdx.x;
    const int c0 = t * 4, c1 = c0 + 1024;

    float4 v0 = *reinterpret_cast<const float4*>(&latents[base + c0]);
    float4 v1 = *reinterpret_cast<const float4*>(&latents[base + c1]);
    float s = v0.x + v0.y + v0.z + v0.w + v1.x + v1.y + v1.z + v1.w;
    float mean = block_sum256(s, red) * (1.0f / Dc);
    float d0x = v0.x - mean, d0y = v0.y - mean, d0z = v0.z - mean, d0w = v0.w - mean;
    float d1x = v1.x - mean, d1y = v1.y - mean, d1z = v1.z - mean, d1w = v1.w - mean;
    float sq = d0x*d0x + d0y*d0y + d0z*d0z + d0w*d0w + d1x*d1x + d1y*d1y + d1z*d1z + d1w*d1w;
    float var = block_sum256(sq, red) * (1.0f / Dc);
    float rstd = rsqrtf(var + 1e-5f);

    const float* sh_t = t_emb + (size_t)(bidx * 3 + 0) * Dc;
    const float* sc_t = t_emb + (size_t)(bidx * 3 + 1) * Dc;

    #pragma unroll
    for (int half = 0; half < 2; half++) {
        int c = (half == 0) ? c0 : c1;
        float dv[4] = { (half ? d1x : d0x), (half ? d1y : d0y),
                        (half ? d1z : d0z), (half ? d1w : d0w) };
        float4 sht = *reinterpret_cast<const float4*>(&sh_t[c]);
        float4 sct = *reinterpret_cast<const float4*>(&sc_t[c]);
        float4 shs = *reinterpret_cast<const float4*>(&ssg[c]);
        float4 scs = *reinterpret_cast<const float4*>(&ssg[Dc + c]);
        float4 o;
        o.x = dv[0]*rstd * (1.0f + sct.x + scs.x) + sht.x + shs.x;
        o.y = dv[1]*rstd * (1.0f + sct.y + scs.y) + sht.y + shs.y;
        o.z = dv[2]*rstd * (1.0f + sct.z + scs.z) + sht.z + shs.z;
        o.w = dv[3]*rstd * (1.0f + sct.w + scs.w) + sht.w + shs.w;
        split_store4(out_hi, out_lo, base + c, o);
    }
}

// ---------------------------------------------------------------------------
// Launch — R13 two-branch graph (best-known config):
//   s0: split_Wkv -> ln_x -> kv GEMM -> (wait evB) flash -> (wait evC) out GEMM
//   sB: split_Wq -> ln_lat -> q GEMM [evB] -> split_Wo [evC]
// ---------------------------------------------------------------------------
extern "C" void kernel_launch(void* const* d_in, const int* in_sizes, int n_in,
                              void* d_out, int out_size) {
    (void)in_sizes; (void)n_in; (void)out_size;
    const float* x       = (const float*)d_in[0];
    const float* latents = (const float*)d_in[1];
    const float* t_emb   = (const float*)d_in[2];
    const int*   q_lens  = (const int*)  d_in[3];
    const int*   k_lens  = (const int*)  d_in[4];
    const float* ln_kv_w = (const float*)d_in[5];
    const float* ln_kv_b = (const float*)d_in[6];
    const float* ssg     = (const float*)d_in[7];
    const float* Wq      = (const float*)d_in[8];
    const float* bq      = (const float*)d_in[9];
    const float* Wkv     = (const float*)d_in[10];
    const float* bkv     = (const float*)d_in[11];
    const float* Wo      = (const float*)d_in[12];
    const float* bo      = (const float*)d_in[13];
    float* out = (float*)d_out;

    bf16 *xk_h, *xk_l, *lat_h, *lat_l, *q_h, *q_l, *kv_h, *kv_l;
    bf16 *at_h, *at_l, *wq_h, *wq_l, *wkv_h, *wkv_l, *wo_h, *wo_l;
    cudaGetSymbolAddress((void**)&xk_h, g_xk_hi);   cudaGetSymbolAddress((void**)&xk_l, g_xk_lo);
    cudaGetSymbolAddress((void**)&lat_h, g_lat_hi); cudaGetSymbolAddress((void**)&lat_l, g_lat_lo);
    cudaGetSymbolAddress((void**)&q_h, g_q_hi);     cudaGetSymbolAddress((void**)&q_l, g_q_lo);
    cudaGetSymbolAddress((void**)&kv_h, g_kv_hi);   cudaGetSymbolAddress((void**)&kv_l, g_kv_lo);
    cudaGetSymbolAddress((void**)&at_h, g_at_hi);   cudaGetSymbolAddress((void**)&at_l, g_at_lo);
    cudaGetSymbolAddress((void**)&wq_h, g_wq_hi);   cudaGetSymbolAddress((void**)&wq_l, g_wq_lo);
    cudaGetSymbolAddress((void**)&wkv_h, g_wkv_hi); cudaGetSymbolAddress((void**)&wkv_l, g_wkv_lo);
    cudaGetSymbolAddress((void**)&wo_h, g_wo_hi);   cudaGetSymbolAddress((void**)&wo_l, g_wo_lo);

    constexpr int SMEM_F256 = 2 * (2 * 128 * 72 * 2 + 2 * 64 * 264 * 2);  // 208896
    cudaFuncSetAttribute(gemm_ks<256, 1>, cudaFuncAttributeMaxDynamicSharedMemorySize, SMEM_F256);
    cudaFuncSetAttribute(gemm_ks<256, 2>, cudaFuncAttributeMaxDynamicSharedMemorySize, SMEM_F256);
    cudaFuncSetAttribute(flash_kernel, cudaFuncAttributeMaxDynamicSharedMemorySize, FL_SMEM);

    // Side stream + events, created once on the first (non-captured) call.
    static cudaStream_t sB = nullptr;
    static cudaEvent_t evRoot = nullptr, evB = nullptr, evC = nullptr;
    if (sB == nullptr) {
        cudaStreamCreateWithFlags(&sB, cudaStreamNonBlocking);
        cudaEventCreateWithFlags(&evRoot, cudaEventDisableTiming);
        cudaEventCreateWithFlags(&evB, cudaEventDisableTiming);
        cudaEventCreateWithFlags(&evC, cudaEventDisableTiming);
    }
    cudaStream_t s0 = 0;

    // fork
    cudaEventRecord(evRoot, s0);
    cudaStreamWaitEvent(sB, evRoot, 0);

    // ---- branch B (independent q chain) ----
    split_kernel<<<2048, 256, 0, sB>>>(Wq, wq_h, wq_l, Dc * Dc / 4);
    ln_lat_kernel<<<Bc * Lc, 256, 0, sB>>>(latents, t_emb, ssg, lat_h, lat_l);
    gemm_ks<256, 1><<<dim3(Dc / 256, (Bc * Lc) / 128, 1), 256, SMEM_F256, sB>>>(
        lat_h, lat_l, wq_h, wq_l, nullptr, q_h, q_l, bq, nullptr, nullptr,
        nullptr, Lc,
        Dc, Dc, Dc, Dc);
    cudaEventRecord(evB, sB);                     // flash dependency: q done
    split_kernel<<<2048, 256, 0, sB>>>(Wo, wo_h, wo_l, Dc * Dc / 4);
    cudaEventRecord(evC, sB);                     // out GEMM dependency: Wo done

    // ---- branch A (kv chain, on the capture stream) ----
    split_kernel<<<2048, 256, 0, s0>>>(Wkv, wkv_h, wkv_l, KVc * 2 * Dc / 4);
    ln_x_kernel<<<Bc * Kc, 256, 0, s0>>>(x, ln_kv_w, ln_kv_b, xk_h, xk_l, k_lens);
    gemm_ks<256, 1><<<dim3(2 * Dc / 256, (Bc * Kc) / 128, 1), 256, SMEM_F256, s0>>>(
        xk_h, xk_l, wkv_h, wkv_l, nullptr, kv_h, kv_l, bkv, nullptr, nullptr,
        k_lens, Kc,
        KVc, KVc, 2 * Dc, 2 * Dc);

    // join: flash needs q (branch B) and kv (branch A)
    cudaStreamWaitEvent(s0, evB, 0);

    flash_kernel<<<dim3(1, Lc / 128, Bc * Hc), 256, FL_SMEM, s0>>>(
        q_h, q_l, kv_h, kv_l, at_h, at_l, k_lens, q_lens);

    // out = (at @ Wo + bo) * gate
    cudaStreamWaitEvent(s0, evC, 0);
    gemm_ks<256, 2><<<dim3(Dc / 256, (Bc * Lc) / 128, 1), 256, SMEM_F256, s0>>>(
        at_h, at_l, wo_h, wo_l, out, nullptr, nullptr, bo, t_emb, ssg,
        nullptr, Lc,
        Dc, Dc, Dc, Dc);
}

// round 17
// speedup vs baseline: 1.0485x; 1.0157x over previous
#include <cuda_runtime.h>
#include <cuda_bf16.h>
#include <mma.h>
#include <cstdint>

using namespace nvcuda;
typedef __nv_bfloat16 bf16;

// Problem dims
constexpr int Bc  = 4;
constexpr int Lc  = 512;
constexpr int Dc  = 2048;
constexpr int Hc  = 16;
constexpr int Cc  = 128;
constexpr int KVc = 2048;
constexpr int Kc  = 1024;   // T*LA

// ---------------------------------------------------------------------------
// Scratch (device globals — allocation-free rule)
// ---------------------------------------------------------------------------
__device__ bf16  g_xk_hi[(size_t)Bc * Kc * KVc];
__device__ bf16  g_xk_lo[(size_t)Bc * Kc * KVc];
__device__ bf16  g_lat_hi[(size_t)Bc * Lc * Dc];
__device__ bf16  g_lat_lo[(size_t)Bc * Lc * Dc];
__device__ bf16  g_q_hi[(size_t)Bc * Lc * Dc];
__device__ bf16  g_q_lo[(size_t)Bc * Lc * Dc];
__device__ bf16  g_kv_hi[(size_t)Bc * Kc * 2 * Dc];
__device__ bf16  g_kv_lo[(size_t)Bc * Kc * 2 * Dc];
__device__ bf16  g_at_hi[(size_t)Bc * Lc * Dc];
__device__ bf16  g_at_lo[(size_t)Bc * Lc * Dc];
__device__ bf16  g_wq_hi[(size_t)Dc * Dc];
__device__ bf16  g_wq_lo[(size_t)Dc * Dc];
__device__ bf16  g_wkv_hi[(size_t)KVc * 2 * Dc];
__device__ bf16  g_wkv_lo[(size_t)KVc * 2 * Dc];
__device__ bf16  g_wo_hi[(size_t)Dc * Dc];
__device__ bf16  g_wo_lo[(size_t)Dc * Dc];

// ---------------------------------------------------------------------------
// Helpers
// ---------------------------------------------------------------------------
__device__ __forceinline__ void cp_async16(void* smem_dst, const void* gmem_src) {
    unsigned s = (unsigned)__cvta_generic_to_shared(smem_dst);
    asm volatile("cp.async.cg.shared.global [%0], [%1], 16;\n" :: "r"(s), "l"(gmem_src));
}
__device__ __forceinline__ void cp_commit() { asm volatile("cp.async.commit_group;\n"); }
__device__ __forceinline__ void cp_wait0()  { asm volatile("cp.async.wait_group 0;\n"); }
__device__ __forceinline__ void cp_wait1()  { asm volatile("cp.async.wait_group 1;\n"); }
__device__ __forceinline__ void cp_wait2()  { asm volatile("cp.async.wait_group 2;\n"); }

struct __align__(8) bf4 { bf16 v[4]; };
__device__ __forceinline__ void split_store4(bf16* hi, bf16* lo, size_t off, float4 f) {
    bf4 H, L;
    float ff[4] = { f.x, f.y, f.z, f.w };
    #pragma unroll
    for (int e = 0; e < 4; e++) {
        bf16 h = __float2bfloat16(ff[e]);
        H.v[e] = h;
        L.v[e] = __float2bfloat16(ff[e] - __bfloat162float(h));
    }
    *reinterpret_cast<bf4*>(hi + off) = H;
    *reinterpret_cast<bf4*>(lo + off) = L;
}

__device__ __forceinline__ float warp_sum(float v) {
    #pragma unroll
    for (int o = 16; o > 0; o >>= 1) v += __shfl_xor_sync(0xffffffffu, v, o);
    return v;
}
__device__ __forceinline__ float block_sum256(float v, float* red) {
    int lane = threadIdx.x & 31, w = threadIdx.x >> 5;
    v = warp_sum(v);
    if (lane == 0) red[w] = v;
    __syncthreads();
    if (w == 0) {
        float t = (lane < 8) ? red[lane] : 0.0f;
        t = warp_sum(t);
        if (lane == 0) red[32] = t;
    }
    __syncthreads();
    float r = red[32];
    __syncthreads();
    return r;
}

// ---------------------------------------------------------------------------
// fp32 -> bf16 hi/lo splitter (weights)
// ---------------------------------------------------------------------------
__global__ void split_kernel(const float* __restrict__ W,
                             bf16* __restrict__ hi, bf16* __restrict__ lo,
                             int total4) {
    int i = blockIdx.x * blockDim.x + threadIdx.x;
    const int stride = gridDim.x * blockDim.x;
    for (; i < total4; i += stride) {
        float4 v = reinterpret_cast<const float4*>(W)[i];
        split_store4(hi, lo, (size_t)i * 4, v);
    }
}

// ---------------------------------------------------------------------------
// bf16x3 GEMM (R7 proven config): 256 threads, 128 x BN tile, warp 64 x BN/4,
// BK=64, 2-stage cp.async double buffer.
// OMODE: 1 bf16 hi/lo (+bias); 2 (acc+bias)*gate fp32.
// mklens/rpb: optional M-tile skip (rows never consumed downstream).
// ---------------------------------------------------------------------------
template <int BN, int OMODE>
__global__ void __launch_bounds__(256)
gemm_ks(const bf16* __restrict__ Ah, const bf16* __restrict__ Al,
        const bf16* __restrict__ Bh, const bf16* __restrict__ Bl,
        float* __restrict__ C, bf16* __restrict__ Ch, bf16* __restrict__ Cl,
        const float* __restrict__ bias,
        const float* __restrict__ t_emb, const float* __restrict__ ssg,
        const int* __restrict__ mklens, int rpb,
        int Kd, int lda, int ldb, int ldc) {
    extern __shared__ char sm[];
    constexpr int APITCH = 72;                       // bf16 pitch, BK=64 (+8 pad)
    constexpr int BPITCH = BN + 8;
    constexpr int ABYTES = 128 * APITCH * 2;         // 18432 per A slice
    constexpr int BBYTES = 64 * (BN + 8) * 2;
    constexpr int STAGE  = 2 * ABYTES + 2 * BBYTES;
    constexpr int WN     = BN / 64;                  // wmma j-tiles per warp

    const int n0 = blockIdx.x * BN;
    const int m0 = blockIdx.y * 128;

    if (mklens) {
        const int bb2 = m0 / rpb;
        if (m0 - bb2 * rpb >= mklens[bb2]) return;   // dead M tile
    }

    const int tid  = threadIdx.x;
    const int warp = tid >> 5;
    const int lane = tid & 31;
    const int wm   = warp & 1;
    const int wn   = warp >> 1;

    wmma::fragment<wmma::accumulator, 16, 16, 16, float> acc[4][WN];
    #pragma unroll
    for (int i = 0; i < 4; i++)
        #pragma unroll
        for (int j = 0; j < WN; j++) wmma::fill_fragment(acc[i][j], 0.0f);

    auto load_stage = [&](int st, int k0) {
        char* base = sm + st * STAGE;
        bf16* dAh = (bf16*)base;
        bf16* dAl = (bf16*)(base + ABYTES);
        bf16* dBh = (bf16*)(base + 2 * ABYTES);
        bf16* dBl = (bf16*)(base + 2 * ABYTES + BBYTES);
        #pragma unroll
        for (int i = 0; i < 8; i++) {
            int idx = tid + (i << 8);
            int l = idx & 1023;
            int r = l >> 3, c = (l & 7) * 8;
            const bf16* src = (idx < 1024 ? Ah : Al) + (size_t)(m0 + r) * lda + k0 + c;
            cp_async16((idx < 1024 ? dAh : dAl) + r * APITCH + c, src);
        }
        constexpr int CPR = BN / 8;
        #pragma unroll
        for (int i = 0; i < BN / 16; i++) {
            int idx = tid + (i << 8);
            int l = idx & (8 * BN - 1);
            int r = l / CPR, c = (l % CPR) * 8;
            const bf16* src = (idx < 8 * BN ? Bh : Bl) + (size_t)(k0 + r) * ldb + n0 + c;
            cp_async16((idx < 8 * BN ? dBh : dBl) + r * BPITCH + c, src);
        }
    };

    const int nIter = Kd >> 6;
    load_stage(0, 0); cp_commit();
    if (nIter > 1) { load_stage(1, 64); cp_commit(); }

    for (int it = 0; it < nIter; ++it) {
        if (it + 1 < nIter) cp_wait1(); else cp_wait0();
        __syncthreads();

        char* base = sm + (it & 1) * STAGE;
        const bf16* sAh = (const bf16*)base;
        const bf16* sAl = (const bf16*)(base + ABYTES);
        const bf16* sBh = (const bf16*)(base + 2 * ABYTES);
        const bf16* sBl = (const bf16*)(base + 2 * ABYTES + BBYTES);
        #pragma unroll
        for (int kk = 0; kk < 4; kk++) {
            wmma::fragment<wmma::matrix_a, 16, 16, 16, bf16, wmma::row_major> ah[4], al[4];
            #pragma unroll
            for (int i = 0; i < 4; i++) {
                wmma::load_matrix_sync(ah[i], sAh + (wm * 64 + 16 * i) * APITCH + kk * 16, APITCH);
                wmma::load_matrix_sync(al[i], sAl + (wm * 64 + 16 * i) * APITCH + kk * 16, APITCH);
            }
            #pragma unroll
            for (int j = 0; j < WN; j++) {
                const int ncol = wn * (BN / 4) + 16 * j;
                wmma::fragment<wmma::matrix_b, 16, 16, 16, bf16, wmma::row_major> bh, bl;
                wmma::load_matrix_sync(bh, sBh + (kk * 16) * BPITCH + ncol, BPITCH);
                wmma::load_matrix_sync(bl, sBl + (kk * 16) * BPITCH + ncol, BPITCH);
                #pragma unroll
                for (int i = 0; i < 4; i++) wmma::mma_sync(acc[i][j], ah[i], bh, acc[i][j]);
                #pragma unroll
                for (int i = 0; i < 4; i++) wmma::mma_sync(acc[i][j], al[i], bh, acc[i][j]);
                #pragma unroll
                for (int i = 0; i < 4; i++) wmma::mma_sync(acc[i][j], ah[i], bl, acc[i][j]);
            }
        }

        if (it + 2 < nIter) {
            __syncthreads();
            load_stage(it & 1, (it + 2) << 6);
            cp_commit();
        }
    }

    __syncthreads();
    float* stag = (float*)sm + warp * 2560;  // 64 x 40 floats per warp
    const int bidx = m0 / Lc;
    #pragma unroll
    for (int p = 0; p < WN / 2; p++) {
        #pragma unroll
        for (int i = 0; i < 4; i++)
            #pragma unroll
            for (int jj = 0; jj < 2; jj++)
                wmma::store_matrix_sync(stag + (16 * i) * 40 + 16 * jj,
                                        acc[i][2 * p + jj], 40, wmma::mem_row_major);
        __syncwarp();
        #pragma unroll
        for (int itr = 0; itr < 16; itr++) {
            int g = lane + itr * 32;
            int r = g >> 3;
            int c = (g & 7) * 4;
            float4 v = *reinterpret_cast<const float4*>(stag + r * 40 + c);
            int gr = m0 + wm * 64 + r;
            int gc = n0 + wn * (BN / 4) + p * 32 + c;
            if constexpr (OMODE == 1) {
                if (bias) {
                    float4 bv = *reinterpret_cast<const float4*>(&bias[gc]);
                    v.x += bv.x; v.y += bv.y; v.z += bv.z; v.w += bv.w;
                }
                split_store4(Ch, Cl, (size_t)gr * ldc + gc, v);
            } else {
                float4 bv = *reinterpret_cast<const float4*>(&bias[gc]);
                float4 g1 = *reinterpret_cast<const float4*>(&t_emb[(size_t)(bidx * 3 + 2) * Dc + gc]);
                float4 g2 = *reinterpret_cast<const float4*>(&ssg[2 * Dc + gc]);
                float4 o;
                o.x = (v.x + bv.x) * (g1.x + g2.x);
                o.y = (v.y + bv.y) * (g1.y + g2.y);
                o.z = (v.z + bv.z) * (g1.z + g2.z);
                o.w = (v.w + bv.w) * (g1.w + g2.w);
                *reinterpret_cast<float4*>(&C[(size_t)gr * ldc + gc]) = o;
            }
        }
        __syncwarp();
    }
}

// ---------------------------------------------------------------------------
// Fused flash attention: scores + (max-free) softmax + P·V + qmask.
// ---------------------------------------------------------------------------
constexpr int FL_QH = 0;        // Q hi  128 x 136 bf16   (34816)
constexpr int FL_QL = 34816;    // Q lo
constexpr int FL_KH = 69632;    // K hi   64 x 136 bf16   (17408)
constexpr int FL_KL = 87040;    // K lo
constexpr int FL_V0 = 104448;   // V stage: + st*34816 ; {hi, lo} 17408 each
constexpr int FL_S  = 174080;   // S fp32 [128][72] (36864); P hi/lo overlay
constexpr int FL_PH = 174080;   // P hi bf16 [128][72] (18432)
constexpr int FL_PL = 192512;   // P lo
constexpr int FL_RS = 210944;   // rowsum float[128]
constexpr int FL_SMEM = 211456;

__global__ void __launch_bounds__(256)
flash_kernel(const bf16* __restrict__ qh, const bf16* __restrict__ ql,
             const bf16* __restrict__ kvh, const bf16* __restrict__ kvl,
             bf16* __restrict__ ath, bf16* __restrict__ atl,
             const int* __restrict__ k_lens, const int* __restrict__ q_lens) {
    extern __shared__ char sm[];
    const int tid = threadIdx.x, warp = tid >> 5, lane = tid & 31;
    const int wm = warp & 1, wn = warp >> 1;
    const int z = blockIdx.z, b = z >> 4, h = z & 15;
    const int m0 = blockIdx.y * 128;
    const int klen = k_lens[b];
    const int qlen = q_lens[b];
    const int nb = (klen + 63) >> 6;
    const float alpha = 0.08838834764831845f;   // 1/sqrt(128)

    float* rowsum = (float*)(sm + FL_RS);
    if (tid < 128) rowsum[tid] = 0.0f;

    const bf16* qbh = qh + ((size_t)(b * Lc + m0) * Dc + h * Cc);
    const bf16* qbl = ql + ((size_t)(b * Lc + m0) * Dc + h * Cc);
    const bf16* kbh = kvh + ((size_t)b * Kc * 2 * Dc + h * Cc);
    const bf16* kbl = kvl + ((size_t)b * Kc * 2 * Dc + h * Cc);
    const bf16* vbh = kvh + ((size_t)b * Kc * 2 * Dc + Dc + h * Cc);
    const bf16* vbl = kvl + ((size_t)b * Kc * 2 * Dc + Dc + h * Cc);

    auto load_k = [&](int kb) {
        #pragma unroll
        for (int i = 0; i < 8; i++) {
            int idx = tid + (i << 8);
            int l = idx & 1023;
            int r = l >> 4, c = (l & 15) * 8;
            const bf16* src = (idx < 1024 ? kbh : kbl) + (size_t)(kb * 64 + r) * (2 * Dc) + c;
            char* dst = sm + (idx < 1024 ? FL_KH : FL_KL);
            cp_async16(dst + r * 272 + c * 2, src);
        }
    };
    auto load_v = [&](int kb) {
        char* vb = sm + FL_V0 + (kb & 1) * 34816;
        #pragma unroll
        for (int i = 0; i < 8; i++) {
            int idx = tid + (i << 8);
            int l = idx & 1023;
            int r = l >> 4, c = (l & 15) * 8;
            const bf16* src = (idx < 1024 ? vbh : vbl) + (size_t)(kb * 64 + r) * (2 * Dc) + c;
            cp_async16(vb + (idx < 1024 ? 0 : 17408) + r * 272 + c * 2, src);
        }
    };

    // prologue: Q (one group), K0, V0
    #pragma unroll
    for (int i = 0; i < 16; i++) {
        int idx = tid + (i << 8);
        int l = idx & 2047;
        int r = l >> 4, c = (l & 15) * 8;
        const bf16* src = (idx < 2048 ? qbh : qbl) + (size_t)r * Dc + c;
        char* dst = sm + (idx < 2048 ? FL_QH : FL_QL);
        cp_async16(dst + r * 272 + c * 2, src);
    }
    cp_commit();
    load_k(0); cp_commit();
    load_v(0); cp_commit();

    const bf16* sQh = (const bf16*)(sm + FL_QH);
    const bf16* sQl = (const bf16*)(sm + FL_QL);
    const bf16* sKh = (const bf16*)(sm + FL_KH);
    const bf16* sKl = (const bf16*)(sm + FL_KL);
    float* Ssm = (float*)(sm + FL_S);
    bf16* Ph = (bf16*)(sm + FL_PH);
    bf16* Pl = (bf16*)(sm + FL_PL);

    wmma::fragment<wmma::accumulator, 16, 16, 16, float> oacc[4][2];
    #pragma unroll
    for (int i = 0; i < 4; i++)
        #pragma unroll
        for (int j = 0; j < 2; j++) wmma::fill_fragment(oacc[i][j], 0.0f);

    for (int kb = 0; kb < nb; ++kb) {
        cp_wait1();          // K(kb) (and Q) arrived
        __syncthreads();

        // ---- S = Q · K^T : warp tile 64(q) x 16(k), acc[4] ----
        {
            wmma::fragment<wmma::accumulator, 16, 16, 16, float> sacc[4];
            #pragma unroll
            for (int i = 0; i < 4; i++) wmma::fill_fragment(sacc[i], 0.0f);
            #pragma unroll
            for (int kk = 0; kk < 8; kk++) {
                wmma::fragment<wmma::matrix_a, 16, 16, 16, bf16, wmma::row_major> ah[4], al[4];
                #pragma unroll
                for (int i = 0; i < 4; i++) {
                    wmma::load_matrix_sync(ah[i], sQh + (wm * 64 + 16 * i) * 136 + kk * 16, 136);
                    wmma::load_matrix_sync(al[i], sQl + (wm * 64 + 16 * i) * 136 + kk * 16, 136);
                }
                wmma::fragment<wmma::matrix_b, 16, 16, 16, bf16, wmma::col_major> bh, bl;
                wmma::load_matrix_sync(bh, sKh + (wn * 16) * 136 + kk * 16, 136);
                wmma::load_matrix_sync(bl, sKl + (wn * 16) * 136 + kk * 16, 136);
                #pragma unroll
                for (int i = 0; i < 4; i++) wmma::mma_sync(sacc[i], ah[i], bh, sacc[i]);
                #pragma unroll
                for (int i = 0; i < 4; i++) wmma::mma_sync(sacc[i], al[i], bh, sacc[i]);
                #pragma unroll
                for (int i = 0; i < 4; i++) wmma::mma_sync(sacc[i], ah[i], bl, sacc[i]);
            }
            #pragma unroll
            for (int i = 0; i < 4; i++)
                wmma::store_matrix_sync(Ssm + (wm * 64 + 16 * i) * 72 + wn * 16,
                                        sacc[i], 72, wmma::mem_row_major);
        }
        __syncthreads();

        // ---- exp (max-free) + P hi/lo + rowsum ----
        {
            const int row = tid >> 1, ch = (tid & 1) << 5;
            float e[32];
            #pragma unroll
            for (int c = 0; c < 32; c++) e[c] = Ssm[row * 72 + ch + c];
            __syncthreads();     // all reads done before P overwrites S
            float ps = 0.0f;
            const int kc0 = kb * 64 + ch;
            #pragma unroll
            for (int c = 0; c < 32; c++) {
                float v = (kc0 + c < klen) ? __expf(e[c] * alpha) : 0.0f;
                ps += v;
                bf16 hi = __float2bfloat16(v);
                Ph[row * 72 + ch + c] = hi;
                Pl[row * 72 + ch + c] = __float2bfloat16(v - __bfloat162float(hi));
            }
            ps += __shfl_xor_sync(0xffffffffu, ps, 1);
            if ((tid & 1) == 0) rowsum[row] += ps;
        }

        const bool more = (kb + 1 < nb);
        if (more) { load_k(kb + 1); cp_commit(); load_v(kb + 1); cp_commit(); }
        if (more) cp_wait2(); else cp_wait0();   // V(kb) arrived
        __syncthreads();                          // P + V visible

        // ---- O += P · V : warp tile 64(q) x 32(c), acc[4][2] ----
        {
            const bf16* sVh = (const bf16*)(sm + FL_V0 + (kb & 1) * 34816);
            const bf16* sVl = (const bf16*)(sm + FL_V0 + (kb & 1) * 34816 + 17408);
            #pragma unroll
            for (int kk = 0; kk < 4; kk++) {
                wmma::fragment<wmma::matrix_a, 16, 16, 16, bf16, wmma::row_major> ah[4], al[4];
                #pragma unroll
                for (int i = 0; i < 4; i++) {
                    wmma::load_matrix_sync(ah[i], Ph + (wm * 64 + 16 * i) * 72 + kk * 16, 72);
                    wmma::load_matrix_sync(al[i], Pl + (wm * 64 + 16 * i) * 72 + kk * 16, 72);
                }
                #pragma unroll
                for (int j = 0; j < 2; j++) {
                    const int ncol = wn * 32 + 16 * j;
                    wmma::fragment<wmma::matrix_b, 16, 16, 16, bf16, wmma::row_major> bh, bl;
                    wmma::load_matrix_sync(bh, sVh + (kk * 16) * 136 + ncol, 136);
                    wmma::load_matrix_sync(bl, sVl + (kk * 16) * 136 + ncol, 136);
                    #pragma unroll
                    for (int i = 0; i < 4; i++) wmma::mma_sync(oacc[i][j], ah[i], bh, oacc[i][j]);
                    #pragma unroll
                    for (int i = 0; i < 4; i++) wmma::mma_sync(oacc[i][j], al[i], bh, oacc[i][j]);
                    #pragma unroll
                    for (int i = 0; i < 4; i++) wmma::mma_sync(oacc[i][j], ah[i], bl, oacc[i][j]);
                }
            }
        }
    }

    // ---- epilogue: scale by 1/rowsum, apply q_lens mask, store bf16 hi/lo ----
    __syncthreads();
    float* stag = (float*)sm + warp * 2560;   // safely inside [0, 81920) = Q/K region
    #pragma unroll
    for (int i = 0; i < 4; i++)
        #pragma unroll
        for (int j = 0; j < 2; j++)
            wmma::store_matrix_sync(stag + (16 * i) * 40 + 16 * j, oacc[i][j], 40,
                                    wmma::mem_row_major);
    __syncwarp();
    #pragma unroll
    for (int itr = 0; itr < 16; itr++) {
        int g = lane + itr * 32;
        int r = g >> 3;
        int c = (g & 7) * 4;
        float4 v = *reinterpret_cast<const float4*>(stag + r * 40 + c);
        int lrow = wm * 64 + r;
        int gc = wn * 32 + c;
        float rinv = (m0 + lrow < qlen) ? (1.0f / rowsum[lrow]) : 0.0f;
        v.x *= rinv; v.y *= rinv; v.z *= rinv; v.w *= rinv;
        split_store4(ath, atl, (size_t)(b * Lc + m0 + lrow) * Dc + h * Cc + gc, v);
    }
}

// ---------------------------------------------------------------------------
// LayerNorm of x -> xk hi/lo (rows >= k_lens[b] skipped: never consumed)
// ---------------------------------------------------------------------------
__global__ void ln_x_kernel(const float* __restrict__ x,
                            const float* __restrict__ w,
                            const float* __restrict__ b,
                            bf16* __restrict__ out_hi, bf16* __restrict__ out_lo,
                            const int* __restrict__ k_lens) {
    __shared__ float red[33];
    const int row = blockIdx.x;
    const int bidx = row >> 10;                   // row / Kc
    if ((row & (Kc - 1)) >= k_lens[bidx]) return; // dead row
    const size_t base = (size_t)row * KVc;
    const int t = threadIdx.x;
    const int c0 = t * 4, c1 = c0 + 1024;

    float4 v0 = *reinterpret_cast<const float4*>(&x[base + c0]);
    float4 v1 = *reinterpret_cast<const float4*>(&x[base + c1]);
    float s = v0.x + v0.y + v0.z + v0.w + v1.x + v1.y + v1.z + v1.w;
    float mean = block_sum256(s, red) * (1.0f / KVc);
    float d0x = v0.x - mean, d0y = v0.y - mean, d0z = v0.z - mean, d0w = v0.w - mean;
    float d1x = v1.x - mean, d1y = v1.y - mean, d1z = v1.z - mean, d1w = v1.w - mean;
    float sq = d0x*d0x + d0y*d0y + d0z*d0z + d0w*d0w + d1x*d1x + d1y*d1y + d1z*d1z + d1w*d1w;
    float var = block_sum256(sq, red) * (1.0f / KVc);
    float rstd = rsqrtf(var + 1e-5f);

    float4 w0 = *reinterpret_cast<const float4*>(&w[c0]);
    float4 w1 = *reinterpret_cast<const float4*>(&w[c1]);
    float4 b0 = *reinterpret_cast<const float4*>(&b[c0]);
    float4 b1 = *reinterpret_cast<const float4*>(&b[c1]);
    split_store4(out_hi, out_lo, base + c0,
        make_float4(d0x*rstd*w0.x + b0.x, d0y*rstd*w0.y + b0.y,
                    d0z*rstd*w0.z + b0.z, d0w*rstd*w0.w + b0.w));
    split_store4(out_hi, out_lo, base + c1,
        make_float4(d1x*rstd*w1.x + b1.x, d1y*rstd*w1.y + b1.y,
                    d1z*rstd*w1.z + b1.z, d1w*rstd*w1.w + b1.w));
}

// ---------------------------------------------------------------------------
// LayerNorm of latents + adaLN modulation -> lat hi/lo
// ---------------------------------------------------------------------------
__global__ void ln_lat_kernel(const float* __restrict__ latents,
                              const float* __restrict__ t_emb,
                              const float* __restrict__ ssg,
                              bf16* __restrict__ out_hi, bf16* __restrict__ out_lo) {
    __shared__ float red[33];
    const int row = blockIdx.x;
    const int bidx = row / Lc;
    const size_t base = (size_t)row * Dc;
    const int t = threadIdx.x;
    const int c0 = t * 4, c1 = c0 + 1024;

    float4 v0 = *reinterpret_cast<const float4*>(&latents[base + c0]);
    float4 v1 = *reinterpret_cast<const float4*>(&latents[base + c1]);
    float s = v0.x + v0.y + v0.z + v0.w + v1.x + v1.y + v1.z + v1.w;
    float mean = block_sum256(s, red) * (1.0f / Dc);
    float d0x = v0.x - mean, d0y = v0.y - mean, d0z = v0.z - mean, d0w = v0.w - mean;
    float d1x = v1.x - mean, d1y = v1.y - mean, d1z = v1.z - mean, d1w = v1.w - mean;
    float sq = d0x*d0x + d0y*d0y + d0z*d0z + d0w*d0w + d1x*d1x + d1y*d1y + d1z*d1z + d1w*d1w;
    float var = block_sum256(sq, red) * (1.0f / Dc);
    float rstd = rsqrtf(var + 1e-5f);

    const float* sh_t = t_emb + (size_t)(bidx * 3 + 0) * Dc;
    const float* sc_t = t_emb + (size_t)(bidx * 3 + 1) * Dc;

    #pragma unroll
    for (int half = 0; half < 2; half++) {
        int c = (half == 0) ? c0 : c1;
        float dv[4] = { (half ? d1x : d0x), (half ? d1y : d0y),
                        (half ? d1z : d0z), (half ? d1w : d0w) };
        float4 sht = *reinterpret_cast<const float4*>(&sh_t[c]);
        float4 sct = *reinterpret_cast<const float4*>(&sc_t[c]);
        float4 shs = *reinterpret_cast<const float4*>(&ssg[c]);
        float4 scs = *reinterpret_cast<const float4*>(&ssg[Dc + c]);
        float4 o;
        o.x = dv[0]*rstd * (1.0f + sct.x + scs.x) + sht.x + shs.x;
        o.y = dv[1]*rstd * (1.0f + sct.y + scs.y) + sht.y + shs.y;
        o.z = dv[2]*rstd * (1.0f + sct.z + scs.z) + sht.z + shs.z;
        o.w = dv[3]*rstd * (1.0f + sct.w + scs.w) + sht.w + shs.w;
        split_store4(out_hi, out_lo, base + c, o);
    }
}

// ---------------------------------------------------------------------------
// Launch — R13 topology with trimmed critical-path front:
//   s0: ln_x -> (wait evKV) kv GEMM -> (wait evB) flash -> (wait evC) out GEMM
//   sB: split_Wkv [evKV] -> split_Wq -> ln_lat -> q GEMM [evB] -> split_Wo [evC]
// ---------------------------------------------------------------------------
extern "C" void kernel_launch(void* const* d_in, const int* in_sizes, int n_in,
                              void* d_out, int out_size) {
    (void)in_sizes; (void)n_in; (void)out_size;
    const float* x       = (const float*)d_in[0];
    const float* latents = (const float*)d_in[1];
    const float* t_emb   = (const float*)d_in[2];
    const int*   q_lens  = (const int*)  d_in[3];
    const int*   k_lens  = (const int*)  d_in[4];
    const float* ln_kv_w = (const float*)d_in[5];
    const float* ln_kv_b = (const float*)d_in[6];
    const float* ssg     = (const float*)d_in[7];
    const float* Wq      = (const float*)d_in[8];
    const float* bq      = (const float*)d_in[9];
    const float* Wkv     = (const float*)d_in[10];
    const float* bkv     = (const float*)d_in[11];
    const float* Wo      = (const float*)d_in[12];
    const float* bo      = (const float*)d_in[13];
    float* out = (float*)d_out;

    bf16 *xk_h, *xk_l, *lat_h, *lat_l, *q_h, *q_l, *kv_h, *kv_l;
    bf16 *at_h, *at_l, *wq_h, *wq_l, *wkv_h, *wkv_l, *wo_h, *wo_l;
    cudaGetSymbolAddress((void**)&xk_h, g_xk_hi);   cudaGetSymbolAddress((void**)&xk_l, g_xk_lo);
    cudaGetSymbolAddress((void**)&lat_h, g_lat_hi); cudaGetSymbolAddress((void**)&lat_l, g_lat_lo);
    cudaGetSymbolAddress((void**)&q_h, g_q_hi);     cudaGetSymbolAddress((void**)&q_l, g_q_lo);
    cudaGetSymbolAddress((void**)&kv_h, g_kv_hi);   cudaGetSymbolAddress((void**)&kv_l, g_kv_lo);
    cudaGetSymbolAddress((void**)&at_h, g_at_hi);   cudaGetSymbolAddress((void**)&at_l, g_at_lo);
    cudaGetSymbolAddress((void**)&wq_h, g_wq_hi);   cudaGetSymbolAddress((void**)&wq_l, g_wq_lo);
    cudaGetSymbolAddress((void**)&wkv_h, g_wkv_hi); cudaGetSymbolAddress((void**)&wkv_l, g_wkv_lo);
    cudaGetSymbolAddress((void**)&wo_h, g_wo_hi);   cudaGetSymbolAddress((void**)&wo_l, g_wo_lo);

    constexpr int SMEM_F256 = 2 * (2 * 128 * 72 * 2 + 2 * 64 * 264 * 2);  // 208896
    cudaFuncSetAttribute(gemm_ks<256, 1>, cudaFuncAttributeMaxDynamicSharedMemorySize, SMEM_F256);
    cudaFuncSetAttribute(gemm_ks<256, 2>, cudaFuncAttributeMaxDynamicSharedMemorySize, SMEM_F256);
    cudaFuncSetAttribute(flash_kernel, cudaFuncAttributeMaxDynamicSharedMemorySize, FL_SMEM);

    // Side stream + events, created once on the first (non-captured) call.
    static cudaStream_t sB = nullptr;
    static cudaEvent_t evRoot = nullptr, evKV = nullptr, evB = nullptr, evC = nullptr;
    if (sB == nullptr) {
        cudaStreamCreateWithFlags(&sB, cudaStreamNonBlocking);
        cudaEventCreateWithFlags(&evRoot, cudaEventDisableTiming);
        cudaEventCreateWithFlags(&evKV, cudaEventDisableTiming);
        cudaEventCreateWithFlags(&evB, cudaEventDisableTiming);
        cudaEventCreateWithFlags(&evC, cudaEventDisableTiming);
    }
    cudaStream_t s0 = 0;

    // fork
    cudaEventRecord(evRoot, s0);
    cudaStreamWaitEvent(sB, evRoot, 0);

    // ---- side stream: Wkv split first (kv GEMM dep), then q chain, then Wo ----
    split_kernel<<<2048, 256, 0, sB>>>(Wkv, wkv_h, wkv_l, KVc * 2 * Dc / 4);
    cudaEventRecord(evKV, sB);                    // kv GEMM dependency: Wkv split done
    split_kernel<<<2048, 256, 0, sB>>>(Wq, wq_h, wq_l, Dc * Dc / 4);
    ln_lat_kernel<<<Bc * Lc, 256, 0, sB>>>(latents, t_emb, ssg, lat_h, lat_l);
    gemm_ks<256, 1><<<dim3(Dc / 256, (Bc * Lc) / 128, 1), 256, SMEM_F256, sB>>>(
        lat_h, lat_l, wq_h, wq_l, nullptr, q_h, q_l, bq, nullptr, nullptr,
        nullptr, Lc,
        Dc, Dc, Dc, Dc);
    cudaEventRecord(evB, sB);                     // flash dependency: q done
    split_kernel<<<2048, 256, 0, sB>>>(Wo, wo_h, wo_l, Dc * Dc / 4);
    cudaEventRecord(evC, sB);                     // out GEMM dependency: Wo done

    // ---- main stream: ln_x immediately (needs only x) ----
    ln_x_kernel<<<Bc * Kc, 256, 0, s0>>>(x, ln_kv_w, ln_kv_b, xk_h, xk_l, k_lens);
    cudaStreamWaitEvent(s0, evKV, 0);             // wait only for the Wkv split
    gemm_ks<256, 1><<<dim3(2 * Dc / 256, (Bc * Kc) / 128, 1), 256, SMEM_F256, s0>>>(
        xk_h, xk_l, wkv_h, wkv_l, nullptr, kv_h, kv_l, bkv, nullptr, nullptr,
        k_lens, Kc,
        KVc, KVc, 2 * Dc, 2 * Dc);

    // join: flash needs q (branch B) and kv (branch A)
    cudaStreamWaitEvent(s0, evB, 0);

    flash_kernel<<<dim3(1, Lc / 128, Bc * Hc), 256, FL_SMEM, s0>>>(
        q_h, q_l, kv_h, kv_l, at_h, at_l, k_lens, q_lens);

    // out = (at @ Wo + bo) * gate
    cudaStreamWaitEvent(s0, evC, 0);
    gemm_ks<256, 2><<<dim3(Dc / 256, (Bc * Lc) / 128, 1), 256, SMEM_F256, s0>>>(
        at_h, at_l, wo_h, wo_l, out, nullptr, nullptr, bo, t_emb, ssg,
        nullptr, Lc,
        Dc, Dc, Dc, Dc);
}